// round 1
// baseline (speedup 1.0000x reference)
#include <cuda_runtime.h>
#include <cuda_bf16.h>
#include <math.h>
#include <stdint.h>

#define SEQ       2048
#define EMBED     1536
#define NHEADS    12
#define HDIM      128
#define QKV_N     (3 * EMBED)         // 4608
#define D2        (HDIM / 2)          // 64
#define ATT_BQ    64
#define ATT_BK    32
#define EPS       1e-5f
#define ATT_SCALE 0.08838834764831843f   // 1/sqrt(128)

// ---------------- scratch (device globals; no runtime allocation) ----------------
__device__ float g_qkv[SEQ * QKV_N];            // [s][3E]
__device__ float g_q  [NHEADS * SEQ * HDIM];    // [h][s][d]  post norm+rope
__device__ float g_k  [NHEADS * SEQ * HDIM];
__device__ float g_v  [NHEADS * SEQ * HDIM];
__device__ float g_ctx[SEQ * EMBED];            // [s][h*d]

// ---------------- SGEMM: C[M,N] = A[M,K] @ B[K,N] + bias[N] ----------------
// 128x128 tile, BK=8, 256 threads, 8x8 per thread. M%128==0, N%128==0, K%8==0.
__global__ __launch_bounds__(256) void sgemm128(
    const float* __restrict__ A, const float* __restrict__ B,
    const float* __restrict__ bias, float* __restrict__ C,
    int M, int N, int K)
{
    __shared__ float As[8][132];   // [k][m], padded
    __shared__ float Bs[8][128];   // [k][n]

    const int tid  = threadIdx.x;
    const int tx   = tid & 15;     // n-group
    const int ty   = tid >> 4;     // m-group
    const int row0 = blockIdx.y * 128;
    const int col0 = blockIdx.x * 128;

    const int aRow = tid >> 1;            // 0..127
    const int aCol = (tid & 1) * 4;       // 0 or 4
    const int bRow = tid >> 5;            // 0..7
    const int bCol = (tid & 31) * 4;      // 0..124

    float acc[8][8];
#pragma unroll
    for (int i = 0; i < 8; i++)
#pragma unroll
        for (int j = 0; j < 8; j++) acc[i][j] = 0.f;

    for (int k0 = 0; k0 < K; k0 += 8) {
        float4 a4 = *(const float4*)(A + (size_t)(row0 + aRow) * K + k0 + aCol);
        As[aCol + 0][aRow] = a4.x;
        As[aCol + 1][aRow] = a4.y;
        As[aCol + 2][aRow] = a4.z;
        As[aCol + 3][aRow] = a4.w;
        *(float4*)(&Bs[bRow][bCol]) =
            *(const float4*)(B + (size_t)(k0 + bRow) * N + col0 + bCol);
        __syncthreads();

#pragma unroll
        for (int kk = 0; kk < 8; kk++) {
            float ra[8], rb[8];
            *(float4*)(ra)     = *(const float4*)(&As[kk][ty * 8]);
            *(float4*)(ra + 4) = *(const float4*)(&As[kk][ty * 8 + 4]);
            *(float4*)(rb)     = *(const float4*)(&Bs[kk][tx * 8]);
            *(float4*)(rb + 4) = *(const float4*)(&Bs[kk][tx * 8 + 4]);
#pragma unroll
            for (int i = 0; i < 8; i++)
#pragma unroll
                for (int j = 0; j < 8; j++)
                    acc[i][j] = fmaf(ra[i], rb[j], acc[i][j]);
        }
        __syncthreads();
    }

    float bj[8];
#pragma unroll
    for (int j = 0; j < 8; j++) bj[j] = bias[col0 + tx * 8 + j];

#pragma unroll
    for (int i = 0; i < 8; i++) {
        float4 o0, o1;
        o0.x = acc[i][0] + bj[0]; o0.y = acc[i][1] + bj[1];
        o0.z = acc[i][2] + bj[2]; o0.w = acc[i][3] + bj[3];
        o1.x = acc[i][4] + bj[4]; o1.y = acc[i][5] + bj[5];
        o1.z = acc[i][6] + bj[6]; o1.w = acc[i][7] + bj[7];
        float* cp = C + (size_t)(row0 + ty * 8 + i) * N + col0 + tx * 8;
        *(float4*)(cp)     = o0;
        *(float4*)(cp + 4) = o1;
    }
}

// ---------------- RMSNorm + RoPE + transpose to [h][s][d] ----------------
// grid (SEQ, NHEADS), 128 threads (one per d)
__global__ __launch_bounds__(128) void norm_rope_kernel(
    const float* __restrict__ cosb, const float* __restrict__ sinb,
    const float* __restrict__ qw,   const float* __restrict__ kw)
{
    const int s = blockIdx.x, h = blockIdx.y, d = threadIdx.x;
    __shared__ float sh[128];
    __shared__ float wsum[4];
    __shared__ float rms_sh;

    const float* base = g_qkv + (size_t)s * QKV_N + h * HDIM;
    const int d2 = (d < D2) ? d : d - D2;
    const float c  = cosb[s * D2 + d2];
    const float sn = sinb[s * D2 + d2];
    const size_t oidx = ((size_t)h * SEQ + s) * HDIM + d;

#pragma unroll
    for (int which = 0; which < 2; which++) {
        const float x = base[which * EMBED + d];
        float v = x * x;
#pragma unroll
        for (int o = 16; o; o >>= 1) v += __shfl_xor_sync(0xffffffffu, v, o);
        if ((d & 31) == 0) wsum[d >> 5] = v;
        __syncthreads();
        if (d == 0)
            rms_sh = rsqrtf((wsum[0] + wsum[1] + wsum[2] + wsum[3]) * (1.0f / HDIM) + EPS);
        __syncthreads();
        const float* w = which ? kw : qw;
        sh[d] = x * rms_sh * w[d];
        __syncthreads();
        float out;
        if (d < D2) out = sh[d] * c - sh[d + D2] * sn;
        else        out = sh[d] * c + sh[d - D2] * sn;
        if (which == 0) g_q[oidx] = out; else g_k[oidx] = out;
        __syncthreads();   // protect sh/wsum/rms_sh reuse
    }
    // V: plain copy/transpose
    g_v[oidx] = base[2 * EMBED + d];
}

// ---------------- segment id: searchsorted(cu[1:], p, 'right') ----------------
__device__ __forceinline__ int segment_of(const int* __restrict__ cu, int ncu, int p) {
    int s = 0;
    for (int i = 1; i < ncu; i++) s += (cu[i] <= p) ? 1 : 0;
    return s;
}

// ---------------- flash attention, block = (64 queries, one head) ----------------
// dynamic smem layout (floats): Qs[64*132] Ks[32*132] Vs[32*132] Sb[64*33] m[64] l[64] a[64]
#define ATT_QS_F   (64 * 132)
#define ATT_KS_F   (32 * 132)
#define ATT_SB_F   (64 * 33)
#define ATT_SMEM_F (ATT_QS_F + 2 * ATT_KS_F + ATT_SB_F + 3 * 64)
#define ATT_SMEM_B (ATT_SMEM_F * 4)

__global__ __launch_bounds__(256) void attn_kernel(const int* __restrict__ cu, int ncu)
{
    extern __shared__ float smem[];
    float* Qs   = smem;
    float* Ks   = Qs + ATT_QS_F;
    float* Vs   = Ks + ATT_KS_F;
    float* Sb   = Vs + ATT_KS_F;
    float* mrow = Sb + ATT_SB_F;
    float* lrow = mrow + 64;
    float* arow = lrow + 64;
    __shared__ int segq[64];
    __shared__ int segk[32];
    __shared__ int krange[2];

    const int h   = blockIdx.y;
    const int q0  = blockIdx.x * ATT_BQ;
    const int tid = threadIdx.x;

    const float* Qh = g_q + (size_t)h * SEQ * HDIM;
    const float* Kh = g_k + (size_t)h * SEQ * HDIM;
    const float* Vh = g_v + (size_t)h * SEQ * HDIM;

    // load Q tile (64x128) into padded smem
    for (int i = tid; i < ATT_BQ * HDIM / 4; i += 256) {
        float4 v = *(const float4*)(Qh + (size_t)q0 * HDIM + i * 4);
        *(float4*)(&Qs[(i >> 5) * 132 + (i & 31) * 4]) = v;
    }
    if (tid < 64) {
        segq[tid] = segment_of(cu, ncu, q0 + tid);
        mrow[tid] = -1e30f;
        lrow[tid] = 0.f;
    }
    if (tid == 0) {
        int s0 = segment_of(cu, ncu, q0);
        int s1 = segment_of(cu, ncu, q0 + ATT_BQ - 1);
        if (s0 == s1) { krange[0] = cu[s0]; krange[1] = cu[s0 + 1]; }
        else          { krange[0] = 0;      krange[1] = SEQ; }
    }
    __syncthreads();

    const int klo = krange[0], khi = krange[1];
    const int tq = tid >> 4;     // 0..15 -> queries tq*4..tq*4+3
    const int td = tid & 15;     // 0..15 -> dims td*8..td*8+7
    float accr[4][8];
#pragma unroll
    for (int r = 0; r < 4; r++)
#pragma unroll
        for (int c = 0; c < 8; c++) accr[r][c] = 0.f;

    const int i0 = (tid >> 3) * 2;   // score tile: 2 queries
    const int j0 = (tid & 7) * 4;    // 4 keys

    for (int kb = klo; kb < khi; kb += ATT_BK) {
        // load K/V tiles (guard tail)
        for (int i = tid; i < ATT_BK * HDIM / 4; i += 256) {
            int gr = kb + (i >> 5);
            float4 vk = make_float4(0.f, 0.f, 0.f, 0.f), vv = vk;
            if (gr < khi) {
                vk = *(const float4*)(Kh + (size_t)gr * HDIM + (i & 31) * 4);
                vv = *(const float4*)(Vh + (size_t)gr * HDIM + (i & 31) * 4);
            }
            *(float4*)(&Ks[(i >> 5) * 132 + (i & 31) * 4]) = vk;
            *(float4*)(&Vs[(i >> 5) * 132 + (i & 31) * 4]) = vv;
        }
        if (tid < ATT_BK)
            segk[tid] = (kb + tid < khi) ? segment_of(cu, ncu, kb + tid) : -1000000;
        __syncthreads();

        // scores: 2x4 per thread
        float sc[2][4];
#pragma unroll
        for (int r = 0; r < 2; r++)
#pragma unroll
            for (int j = 0; j < 4; j++) sc[r][j] = 0.f;

        const float* qp0 = &Qs[i0 * 132];
        const float* qp1 = qp0 + 132;
#pragma unroll 4
        for (int k = 0; k < HDIM; k += 4) {
            float4 qa = *(const float4*)(qp0 + k);
            float4 qb = *(const float4*)(qp1 + k);
#pragma unroll
            for (int j = 0; j < 4; j++) {
                float4 kv = *(const float4*)(&Ks[(j0 + j) * 132 + k]);
                sc[0][j] = fmaf(qa.x, kv.x, fmaf(qa.y, kv.y, fmaf(qa.z, kv.z, fmaf(qa.w, kv.w, sc[0][j]))));
                sc[1][j] = fmaf(qb.x, kv.x, fmaf(qb.y, kv.y, fmaf(qb.z, kv.z, fmaf(qb.w, kv.w, sc[1][j]))));
            }
        }
#pragma unroll
        for (int r = 0; r < 2; r++) {
            int sq = segq[i0 + r];
#pragma unroll
            for (int j = 0; j < 4; j++) {
                float val = sc[r][j] * ATT_SCALE;
                if (sq != segk[j0 + j]) val = -1e30f;
                Sb[(i0 + r) * 33 + j0 + j] = val;
            }
        }
        __syncthreads();

        // online softmax row pass: one thread per query
        if (tid < 64) {
            const int i = tid;
            float mloc = -1e30f;
#pragma unroll 8
            for (int j = 0; j < ATT_BK; j++) mloc = fmaxf(mloc, Sb[i * 33 + j]);
            float mold = mrow[i];
            float mnew = fmaxf(mold, mloc);
            float alpha, lsum = 0.f;
            if (mnew <= -1e29f) {
                alpha = 1.f;
#pragma unroll 8
                for (int j = 0; j < ATT_BK; j++) Sb[i * 33 + j] = 0.f;
            } else {
                alpha = __expf(mold - mnew);
#pragma unroll 8
                for (int j = 0; j < ATT_BK; j++) {
                    float p = __expf(Sb[i * 33 + j] - mnew);
                    Sb[i * 33 + j] = p;
                    lsum += p;
                }
            }
            lrow[i] = lrow[i] * alpha + lsum;
            mrow[i] = mnew;
            arow[i] = alpha;
        }
        __syncthreads();

        // rescale + PV accumulate
#pragma unroll
        for (int r = 0; r < 4; r++) {
            float a = arow[tq * 4 + r];
#pragma unroll
            for (int c = 0; c < 8; c++) accr[r][c] *= a;
        }
#pragma unroll 4
        for (int j = 0; j < ATT_BK; j++) {
            float4 v0 = *(const float4*)(&Vs[j * 132 + td * 8]);
            float4 v1 = *(const float4*)(&Vs[j * 132 + td * 8 + 4]);
#pragma unroll
            for (int r = 0; r < 4; r++) {
                float p = Sb[(tq * 4 + r) * 33 + j];
                accr[r][0] = fmaf(p, v0.x, accr[r][0]);
                accr[r][1] = fmaf(p, v0.y, accr[r][1]);
                accr[r][2] = fmaf(p, v0.z, accr[r][2]);
                accr[r][3] = fmaf(p, v0.w, accr[r][3]);
                accr[r][4] = fmaf(p, v1.x, accr[r][4]);
                accr[r][5] = fmaf(p, v1.y, accr[r][5]);
                accr[r][6] = fmaf(p, v1.z, accr[r][6]);
                accr[r][7] = fmaf(p, v1.w, accr[r][7]);
            }
        }
        __syncthreads();
    }

    // epilogue: normalize and write ctx[s][h*128+d]
#pragma unroll
    for (int r = 0; r < 4; r++) {
        int qi = tq * 4 + r;
        float inv = 1.0f / lrow[qi];
        float4 o0, o1;
        o0.x = accr[r][0] * inv; o0.y = accr[r][1] * inv;
        o0.z = accr[r][2] * inv; o0.w = accr[r][3] * inv;
        o1.x = accr[r][4] * inv; o1.y = accr[r][5] * inv;
        o1.z = accr[r][6] * inv; o1.w = accr[r][7] * inv;
        float* cp = g_ctx + (size_t)(q0 + qi) * EMBED + h * HDIM + td * 8;
        *(float4*)(cp)     = o0;
        *(float4*)(cp + 4) = o1;
    }
}

// ---------------- launch ----------------
extern "C" void kernel_launch(void* const* d_in, const int* in_sizes, int n_in,
                              void* d_out, int out_size)
{
    const float* x      = (const float*)d_in[0];
    const int*   cu     = (const int*)  d_in[1];
    const float* cosb   = (const float*)d_in[2];
    const float* sinb   = (const float*)d_in[3];
    const float* w_qkv  = (const float*)d_in[4];
    const float* b_qkv  = (const float*)d_in[5];
    const float* qw     = (const float*)d_in[6];
    const float* kw     = (const float*)d_in[7];
    const float* w_proj = (const float*)d_in[8];
    const float* b_proj = (const float*)d_in[9];
    float* out = (float*)d_out;
    const int ncu = in_sizes[1];

    float *qkv_p, *ctx_p;
    cudaGetSymbolAddress((void**)&qkv_p, g_qkv);
    cudaGetSymbolAddress((void**)&ctx_p, g_ctx);

    cudaFuncSetAttribute(attn_kernel, cudaFuncAttributeMaxDynamicSharedMemorySize, ATT_SMEM_B);

    // 1) QKV = x @ w_qkv + b_qkv
    sgemm128<<<dim3(QKV_N / 128, SEQ / 128), 256>>>(x, w_qkv, b_qkv, qkv_p, SEQ, QKV_N, EMBED);

    // 2) RMSNorm + RoPE + transpose
    norm_rope_kernel<<<dim3(SEQ, NHEADS), 128>>>(cosb, sinb, qw, kw);

    // 3) flash attention per (qblock, head)
    attn_kernel<<<dim3(SEQ / ATT_BQ, NHEADS), 256, ATT_SMEM_B>>>(cu, ncu);

    // 4) out = ctx @ w_proj + b_proj
    sgemm128<<<dim3(EMBED / 128, SEQ / 128), 256>>>(ctx_p, w_proj, b_proj, out, SEQ, EMBED, EMBED);
}

// round 4
// speedup vs baseline: 1.2223x; 1.2223x over previous
#include <cuda_runtime.h>
#include <cuda_bf16.h>
#include <math.h>
#include <stdint.h>

#define SEQ       2048
#define EMBED     1536
#define NHEADS    12
#define HDIM      128
#define QKV_N     (3 * EMBED)         // 4608
#define K3        (3 * EMBED)         // tripled K for split-bf16 GEMM = 4608
#define D2        (HDIM / 2)          // 64
#define ATT_BQ    64
#define ATT_BK    32
#define EPS       1e-5f
#define ATT_SCALE 0.08838834764831843f   // 1/sqrt(128)

// ---------------- scratch (device globals; no runtime allocation) ----------------
__device__ float g_qkv[SEQ * QKV_N];                    // [s][3E] fp32
__device__ float g_q  [NHEADS * SEQ * HDIM];            // [h][s][d]
__device__ float g_k  [NHEADS * SEQ * HDIM];
__device__ float g_v  [NHEADS * SEQ * HDIM];
__device__ float g_ctx[SEQ * EMBED];                    // [s][h*d]
__device__ __nv_bfloat16 g_Ax   [SEQ * K3];             // split A for QKV gemm
__device__ __nv_bfloat16 g_Actx [SEQ * K3];             // split A for proj gemm
__device__ __nv_bfloat16 g_Wtqkv[QKV_N * K3];           // W_qkv^T split  (N x 3K)
__device__ __nv_bfloat16 g_Wtprj[EMBED * K3];           // W_proj^T split (N x 3K)

// ============================================================================
// helpers (sm_100-legal PTX only: mma.sync / ldmatrix / cp.async)
// ============================================================================
__device__ __forceinline__ uint32_t smem_to_u32(const void* p) {
    uint32_t a;
    asm("{ .reg .u64 t; cvta.to.shared.u64 t, %1; cvt.u32.u64 %0, t; }" : "=r"(a) : "l"(p));
    return a;
}
#define CP_ASYNC16(saddr, gptr) \
    asm volatile("cp.async.cg.shared.global [%0], [%1], 16;" \
        :: "r"(saddr), "l"(gptr) : "memory")
#define CP_COMMIT() asm volatile("cp.async.commit_group;" ::: "memory")
#define CP_WAIT0()  asm volatile("cp.async.wait_group 0;" ::: "memory")
#define CP_WAIT1()  asm volatile("cp.async.wait_group 1;" ::: "memory")

__device__ __forceinline__ void ldm_x4(uint32_t* r, uint32_t addr) {
    asm volatile("ldmatrix.sync.aligned.m8n8.x4.shared.b16 {%0,%1,%2,%3}, [%4];"
        : "=r"(r[0]), "=r"(r[1]), "=r"(r[2]), "=r"(r[3]) : "r"(addr));
}
__device__ __forceinline__ void ldm_x2(uint32_t* r, uint32_t addr) {
    asm volatile("ldmatrix.sync.aligned.m8n8.x2.shared.b16 {%0,%1}, [%2];"
        : "=r"(r[0]), "=r"(r[1]) : "r"(addr));
}
__device__ __forceinline__ void mma_bf16(float* d, const uint32_t* a, const uint32_t* b) {
    asm volatile(
        "mma.sync.aligned.m16n8k16.row.col.f32.bf16.bf16.f32 "
        "{%0,%1,%2,%3}, {%4,%5,%6,%7}, {%8,%9}, {%0,%1,%2,%3};"
        : "+f"(d[0]), "+f"(d[1]), "+f"(d[2]), "+f"(d[3])
        : "r"(a[0]), "r"(a[1]), "r"(a[2]), "r"(a[3]), "r"(b[0]), "r"(b[1]));
}

// ============================================================================
// Split-bf16 conversion kernels
// ============================================================================
__global__ __launch_bounds__(256) void conv_split_A(
    const float* __restrict__ src, __nv_bfloat16* __restrict__ dst, int M, int K)
{
    int idx = blockIdx.x * 256 + threadIdx.x;
    if (idx >= M * K) return;
    int m = idx / K, k = idx - m * K;
    float x  = src[idx];
    __nv_bfloat16 hi = __float2bfloat16(x);
    __nv_bfloat16 lo = __float2bfloat16(x - __bfloat162float(hi));
    __nv_bfloat16* row = dst + (size_t)m * (3 * K);
    row[k]         = hi;
    row[K + k]     = lo;
    row[2 * K + k] = hi;
}

// W (K x N fp32, row-major) -> Wt (N x 3K bf16): [0,K)=hi, [K,2K)=hi, [2K,3K)=lo
__global__ __launch_bounds__(256) void conv_split_Wt(
    const float* __restrict__ W, __nv_bfloat16* __restrict__ Wt, int K, int N)
{
    __shared__ float tile[32][33];
    int k0 = blockIdx.x * 32, n0 = blockIdx.y * 32;
    int tx = threadIdx.x, ty = threadIdx.y;   // block (32, 8)
#pragma unroll
    for (int r = 0; r < 32; r += 8)
        tile[ty + r][tx] = W[(size_t)(k0 + ty + r) * N + n0 + tx];
    __syncthreads();
#pragma unroll
    for (int r = 0; r < 32; r += 8) {
        int n = n0 + ty + r, k = k0 + tx;
        float x  = tile[tx][ty + r];
        __nv_bfloat16 hi = __float2bfloat16(x);
        __nv_bfloat16 lo = __float2bfloat16(x - __bfloat162float(hi));
        __nv_bfloat16* row = Wt + (size_t)n * (3 * K);
        row[k]         = hi;
        row[K + k]     = hi;
        row[2 * K + k] = lo;
    }
}

// ============================================================================
// mma.sync GEMM: C[M,N] = A[M,k3] @ Bt[N,k3]^T + bias[N]
// CTA 128x128, BK=32, 256 threads = 8 warps (warp tile 32x64),
// cp.async double buffer, ldmatrix fragments, HMMA bf16, fp32 accum.
// ============================================================================
#define MM_BM  128
#define MM_BN  128
#define MM_BK  32
#define MM_PAD 40    // bf16 per smem row (32 data + 8 pad) -> conflict-free ldmatrix

__global__ __launch_bounds__(256) void gemm_mma(
    const __nv_bfloat16* __restrict__ A, const __nv_bfloat16* __restrict__ Bt,
    const float* __restrict__ bias, float* __restrict__ C, int N, int k3)
{
    __shared__ __nv_bfloat16 As[2][MM_BM * MM_PAD];
    __shared__ __nv_bfloat16 Bs[2][MM_BN * MM_PAD];

    const int tid    = threadIdx.x;
    const int lane   = tid & 31;
    const int wid    = tid >> 5;
    const int warp_m = wid & 3;        // 4 warps over M: 32 rows each
    const int warp_n = wid >> 2;       // 2 warps over N: 64 cols each
    const int m0 = blockIdx.y * MM_BM;
    const int n0 = blockIdx.x * MM_BN;
    const int nchunk = k3 / MM_BK;     // 144

    // ---- global->smem staging (cp.async), each thread: 2 rows x 16B for A and B
    const int ldr = tid >> 2;              // 0..63
    const int lds = (tid & 3) * 8;         // bf16 element offset in row
    const __nv_bfloat16* aG = A  + (size_t)(m0 + ldr) * k3 + lds;
    const __nv_bfloat16* bG = Bt + (size_t)(n0 + ldr) * k3 + lds;
    const uint32_t As_u = smem_to_u32(&As[0][0]);
    const uint32_t Bs_u = smem_to_u32(&Bs[0][0]);
    const uint32_t aS = As_u + (uint32_t)(ldr * MM_PAD + lds) * 2;
    const uint32_t bS = Bs_u + (uint32_t)(ldr * MM_PAD + lds) * 2;
    const uint32_t bufStrideA = MM_BM * MM_PAD * 2;
    const uint32_t bufStrideB = MM_BN * MM_PAD * 2;
    const uint32_t rowHalf = 64 * MM_PAD * 2;

    float acc[2][8][4];
#pragma unroll
    for (int mt = 0; mt < 2; mt++)
#pragma unroll
        for (int nt = 0; nt < 8; nt++)
#pragma unroll
            for (int q = 0; q < 4; q++) acc[mt][nt][q] = 0.f;

    // fragment smem addresses (per warp), + buf offset + ks*32 bytes at use
    uint32_t aAddr[2], bAddr[8];
#pragma unroll
    for (int mt = 0; mt < 2; mt++) {
        int r = warp_m * 32 + mt * 16 + (lane & 15);
        int c = (lane >> 4) * 8;
        aAddr[mt] = As_u + (uint32_t)(r * MM_PAD + c) * 2;
    }
#pragma unroll
    for (int nt = 0; nt < 8; nt++) {
        int r = warp_n * 64 + nt * 8 + (lane & 7);
        int c = ((lane >> 3) & 1) * 8;
        bAddr[nt] = Bs_u + (uint32_t)(r * MM_PAD + c) * 2;
    }

    // preload chunk 0
    CP_ASYNC16(aS,            aG);
    CP_ASYNC16(aS + rowHalf,  aG + (size_t)64 * k3);
    CP_ASYNC16(bS,            bG);
    CP_ASYNC16(bS + rowHalf,  bG + (size_t)64 * k3);
    CP_COMMIT();

    for (int c = 0; c < nchunk; ++c) {
        const int buf = c & 1;
        if (c + 1 < nchunk) {
            const int nb = buf ^ 1;
            const __nv_bfloat16* ag = aG + (c + 1) * MM_BK;
            const __nv_bfloat16* bg = bG + (c + 1) * MM_BK;
            CP_ASYNC16(aS + nb * bufStrideA,            ag);
            CP_ASYNC16(aS + nb * bufStrideA + rowHalf,  ag + (size_t)64 * k3);
            CP_ASYNC16(bS + nb * bufStrideB,            bg);
            CP_ASYNC16(bS + nb * bufStrideB + rowHalf,  bg + (size_t)64 * k3);
            CP_COMMIT();
            CP_WAIT1();
        } else {
            CP_WAIT0();
        }
        __syncthreads();

        const uint32_t aOff = buf * bufStrideA;
        const uint32_t bOff = buf * bufStrideB;
#pragma unroll
        for (int ks = 0; ks < 2; ++ks) {       // k = ks*16 within chunk
            uint32_t af[2][4], bf[8][2];
#pragma unroll
            for (int mt = 0; mt < 2; mt++) ldm_x4(af[mt], aAddr[mt] + aOff + ks * 32);
#pragma unroll
            for (int nt = 0; nt < 8; nt++) ldm_x2(bf[nt], bAddr[nt] + bOff + ks * 32);
#pragma unroll
            for (int mt = 0; mt < 2; mt++)
#pragma unroll
                for (int nt = 0; nt < 8; nt++)
                    mma_bf16(acc[mt][nt], af[mt], bf[nt]);
        }
        __syncthreads();
    }

    // ---- epilogue: write with bias
    const int erow = lane >> 2;
    const int ecol = (lane & 3) * 2;
#pragma unroll
    for (int mt = 0; mt < 2; mt++) {
        int row = m0 + warp_m * 32 + mt * 16 + erow;
#pragma unroll
        for (int nt = 0; nt < 8; nt++) {
            int col = n0 + warp_n * 64 + nt * 8 + ecol;
            float b0 = bias[col], b1 = bias[col + 1];
            float* c0 = C + (size_t)row * N + col;
            float* c1 = C + (size_t)(row + 8) * N + col;
            c0[0] = acc[mt][nt][0] + b0;
            c0[1] = acc[mt][nt][1] + b1;
            c1[0] = acc[mt][nt][2] + b0;
            c1[1] = acc[mt][nt][3] + b1;
        }
    }
}

// ============================================================================
// RMSNorm + RoPE + transpose to [h][s][d]
// ============================================================================
__global__ __launch_bounds__(128) void norm_rope_kernel(
    const float* __restrict__ cosb, const float* __restrict__ sinb,
    const float* __restrict__ qw,   const float* __restrict__ kw)
{
    const int s = blockIdx.x, h = blockIdx.y, d = threadIdx.x;
    __shared__ float sh[128];
    __shared__ float wsum[4];
    __shared__ float rms_sh;

    const float* base = g_qkv + (size_t)s * QKV_N + h * HDIM;
    const int d2 = (d < D2) ? d : d - D2;
    const float c  = cosb[s * D2 + d2];
    const float sn = sinb[s * D2 + d2];
    const size_t oidx = ((size_t)h * SEQ + s) * HDIM + d;

#pragma unroll
    for (int which = 0; which < 2; which++) {
        const float x = base[which * EMBED + d];
        float v = x * x;
#pragma unroll
        for (int o = 16; o; o >>= 1) v += __shfl_xor_sync(0xffffffffu, v, o);
        if ((d & 31) == 0) wsum[d >> 5] = v;
        __syncthreads();
        if (d == 0)
            rms_sh = rsqrtf((wsum[0] + wsum[1] + wsum[2] + wsum[3]) * (1.0f / HDIM) + EPS);
        __syncthreads();
        const float* w = which ? kw : qw;
        sh[d] = x * rms_sh * w[d];
        __syncthreads();
        float out;
        if (d < D2) out = sh[d] * c - sh[d + D2] * sn;
        else        out = sh[d] * c + sh[d - D2] * sn;
        if (which == 0) g_q[oidx] = out; else g_k[oidx] = out;
        __syncthreads();
    }
    g_v[oidx] = base[2 * EMBED + d];
}

// ---------------- segment id ----------------
__device__ __forceinline__ int segment_of(const int* __restrict__ cu, int ncu, int p) {
    int s = 0;
    for (int i = 1; i < ncu; i++) s += (cu[i] <= p) ? 1 : 0;
    return s;
}

// ============================================================================
// flash attention (SIMT)
// ============================================================================
#define ATT_QS_F   (64 * 132)
#define ATT_KS_F   (32 * 132)
#define ATT_SB_F   (64 * 33)
#define ATT_SMEM_F (ATT_QS_F + 2 * ATT_KS_F + ATT_SB_F + 3 * 64)
#define ATT_SMEM_B (ATT_SMEM_F * 4)

__global__ __launch_bounds__(256) void attn_kernel(const int* __restrict__ cu, int ncu)
{
    extern __shared__ float smemf[];
    float* Qs   = smemf;
    float* Ks   = Qs + ATT_QS_F;
    float* Vs   = Ks + ATT_KS_F;
    float* Sb   = Vs + ATT_KS_F;
    float* mrow = Sb + ATT_SB_F;
    float* lrow = mrow + 64;
    float* arow = lrow + 64;
    __shared__ int segq[64];
    __shared__ int segk[32];
    __shared__ int krange[2];

    const int h   = blockIdx.y;
    const int q0  = blockIdx.x * ATT_BQ;
    const int tid = threadIdx.x;

    const float* Qh = g_q + (size_t)h * SEQ * HDIM;
    const float* Kh = g_k + (size_t)h * SEQ * HDIM;
    const float* Vh = g_v + (size_t)h * SEQ * HDIM;

    for (int i = tid; i < ATT_BQ * HDIM / 4; i += 256) {
        float4 v = *(const float4*)(Qh + (size_t)q0 * HDIM + i * 4);
        *(float4*)(&Qs[(i >> 5) * 132 + (i & 31) * 4]) = v;
    }
    if (tid < 64) {
        segq[tid] = segment_of(cu, ncu, q0 + tid);
        mrow[tid] = -1e30f;
        lrow[tid] = 0.f;
    }
    if (tid == 0) {
        int s0 = segment_of(cu, ncu, q0);
        int s1 = segment_of(cu, ncu, q0 + ATT_BQ - 1);
        if (s0 == s1) { krange[0] = cu[s0]; krange[1] = cu[s0 + 1]; }
        else          { krange[0] = 0;      krange[1] = SEQ; }
    }
    __syncthreads();

    const int klo = krange[0], khi = krange[1];
    const int tq = tid >> 4;
    const int td = tid & 15;
    float accr[4][8];
#pragma unroll
    for (int r = 0; r < 4; r++)
#pragma unroll
        for (int c = 0; c < 8; c++) accr[r][c] = 0.f;

    const int i0 = (tid >> 3) * 2;
    const int j0 = (tid & 7) * 4;

    for (int kb = klo; kb < khi; kb += ATT_BK) {
        for (int i = tid; i < ATT_BK * HDIM / 4; i += 256) {
            int gr = kb + (i >> 5);
            float4 vk = make_float4(0.f, 0.f, 0.f, 0.f), vv = vk;
            if (gr < khi) {
                vk = *(const float4*)(Kh + (size_t)gr * HDIM + (i & 31) * 4);
                vv = *(const float4*)(Vh + (size_t)gr * HDIM + (i & 31) * 4);
            }
            *(float4*)(&Ks[(i >> 5) * 132 + (i & 31) * 4]) = vk;
            *(float4*)(&Vs[(i >> 5) * 132 + (i & 31) * 4]) = vv;
        }
        if (tid < ATT_BK)
            segk[tid] = (kb + tid < khi) ? segment_of(cu, ncu, kb + tid) : -1000000;
        __syncthreads();

        float sc[2][4];
#pragma unroll
        for (int r = 0; r < 2; r++)
#pragma unroll
            for (int j = 0; j < 4; j++) sc[r][j] = 0.f;

        const float* qp0 = &Qs[i0 * 132];
        const float* qp1 = qp0 + 132;
#pragma unroll 4
        for (int k = 0; k < HDIM; k += 4) {
            float4 qa = *(const float4*)(qp0 + k);
            float4 qb = *(const float4*)(qp1 + k);
#pragma unroll
            for (int j = 0; j < 4; j++) {
                float4 kv = *(const float4*)(&Ks[(j0 + j) * 132 + k]);
                sc[0][j] = fmaf(qa.x, kv.x, fmaf(qa.y, kv.y, fmaf(qa.z, kv.z, fmaf(qa.w, kv.w, sc[0][j]))));
                sc[1][j] = fmaf(qb.x, kv.x, fmaf(qb.y, kv.y, fmaf(qb.z, kv.z, fmaf(qb.w, kv.w, sc[1][j]))));
            }
        }
#pragma unroll
        for (int r = 0; r < 2; r++) {
            int sq = segq[i0 + r];
#pragma unroll
            for (int j = 0; j < 4; j++) {
                float val = sc[r][j] * ATT_SCALE;
                if (sq != segk[j0 + j]) val = -1e30f;
                Sb[(i0 + r) * 33 + j0 + j] = val;
            }
        }
        __syncthreads();

        if (tid < 64) {
            const int i = tid;
            float mloc = -1e30f;
#pragma unroll 8
            for (int j = 0; j < ATT_BK; j++) mloc = fmaxf(mloc, Sb[i * 33 + j]);
            float mold = mrow[i];
            float mnew = fmaxf(mold, mloc);
            float alpha, lsum = 0.f;
            if (mnew <= -1e29f) {
                alpha = 1.f;
#pragma unroll 8
                for (int j = 0; j < ATT_BK; j++) Sb[i * 33 + j] = 0.f;
            } else {
                alpha = __expf(mold - mnew);
#pragma unroll 8
                for (int j = 0; j < ATT_BK; j++) {
                    float p = __expf(Sb[i * 33 + j] - mnew);
                    Sb[i * 33 + j] = p;
                    lsum += p;
                }
            }
            lrow[i] = lrow[i] * alpha + lsum;
            mrow[i] = mnew;
            arow[i] = alpha;
        }
        __syncthreads();

#pragma unroll
        for (int r = 0; r < 4; r++) {
            float a = arow[tq * 4 + r];
#pragma unroll
            for (int c = 0; c < 8; c++) accr[r][c] *= a;
        }
#pragma unroll 4
        for (int j = 0; j < ATT_BK; j++) {
            float4 v0 = *(const float4*)(&Vs[j * 132 + td * 8]);
            float4 v1 = *(const float4*)(&Vs[j * 132 + td * 8 + 4]);
#pragma unroll
            for (int r = 0; r < 4; r++) {
                float p = Sb[(tq * 4 + r) * 33 + j];
                accr[r][0] = fmaf(p, v0.x, accr[r][0]);
                accr[r][1] = fmaf(p, v0.y, accr[r][1]);
                accr[r][2] = fmaf(p, v0.z, accr[r][2]);
                accr[r][3] = fmaf(p, v0.w, accr[r][3]);
                accr[r][4] = fmaf(p, v1.x, accr[r][4]);
                accr[r][5] = fmaf(p, v1.y, accr[r][5]);
                accr[r][6] = fmaf(p, v1.z, accr[r][6]);
                accr[r][7] = fmaf(p, v1.w, accr[r][7]);
            }
        }
        __syncthreads();
    }

#pragma unroll
    for (int r = 0; r < 4; r++) {
        int qi = tq * 4 + r;
        float inv = 1.0f / lrow[qi];
        float4 o0, o1;
        o0.x = accr[r][0] * inv; o0.y = accr[r][1] * inv;
        o0.z = accr[r][2] * inv; o0.w = accr[r][3] * inv;
        o1.x = accr[r][4] * inv; o1.y = accr[r][5] * inv;
        o1.z = accr[r][6] * inv; o1.w = accr[r][7] * inv;
        float* cp = g_ctx + (size_t)(q0 + qi) * EMBED + h * HDIM + td * 8;
        *(float4*)(cp)     = o0;
        *(float4*)(cp + 4) = o1;
    }
}

// ============================================================================
// launch
// ============================================================================
extern "C" void kernel_launch(void* const* d_in, const int* in_sizes, int n_in,
                              void* d_out, int out_size)
{
    const float* x      = (const float*)d_in[0];
    const int*   cu     = (const int*)  d_in[1];
    const float* cosb   = (const float*)d_in[2];
    const float* sinb   = (const float*)d_in[3];
    const float* w_qkv  = (const float*)d_in[4];
    const float* b_qkv  = (const float*)d_in[5];
    const float* qw     = (const float*)d_in[6];
    const float* kw     = (const float*)d_in[7];
    const float* w_proj = (const float*)d_in[8];
    const float* b_proj = (const float*)d_in[9];
    float* out = (float*)d_out;
    const int ncu = in_sizes[1];

    float *qkv_p, *ctx_p;
    __nv_bfloat16 *Ax_p, *Actx_p, *Wtqkv_p, *Wtprj_p;
    cudaGetSymbolAddress((void**)&qkv_p,   g_qkv);
    cudaGetSymbolAddress((void**)&ctx_p,   g_ctx);
    cudaGetSymbolAddress((void**)&Ax_p,    g_Ax);
    cudaGetSymbolAddress((void**)&Actx_p,  g_Actx);
    cudaGetSymbolAddress((void**)&Wtqkv_p, g_Wtqkv);
    cudaGetSymbolAddress((void**)&Wtprj_p, g_Wtprj);

    cudaFuncSetAttribute(attn_kernel, cudaFuncAttributeMaxDynamicSharedMemorySize, ATT_SMEM_B);

    // split conversions
    conv_split_A<<<(SEQ * EMBED + 255) / 256, 256>>>(x, Ax_p, SEQ, EMBED);
    conv_split_Wt<<<dim3(EMBED / 32, QKV_N / 32), dim3(32, 8)>>>(w_qkv, Wtqkv_p, EMBED, QKV_N);
    conv_split_Wt<<<dim3(EMBED / 32, EMBED / 32), dim3(32, 8)>>>(w_proj, Wtprj_p, EMBED, EMBED);

    // 1) QKV = x @ w_qkv + b_qkv   (HMMA bf16 split)
    gemm_mma<<<dim3(QKV_N / MM_BN, SEQ / MM_BM), 256>>>(Ax_p, Wtqkv_p, b_qkv, qkv_p, QKV_N, K3);

    // 2) RMSNorm + RoPE + transpose
    norm_rope_kernel<<<dim3(SEQ, NHEADS), 128>>>(cosb, sinb, qw, kw);

    // 3) flash attention
    attn_kernel<<<dim3(SEQ / ATT_BQ, NHEADS), 256, ATT_SMEM_B>>>(cu, ncu);

    // 4) out = ctx @ w_proj + b_proj   (HMMA bf16 split)
    conv_split_A<<<(SEQ * EMBED + 255) / 256, 256>>>(ctx_p, Actx_p, SEQ, EMBED);
    gemm_mma<<<dim3(EMBED / MM_BN, SEQ / MM_BM), 256>>>(Actx_p, Wtprj_p, b_proj, out, EMBED, K3);
}

// round 5
// speedup vs baseline: 3.1802x; 2.6017x over previous
#include <cuda_runtime.h>
#include <cuda_bf16.h>
#include <math.h>
#include <stdint.h>

#define SEQ       2048
#define EMBED     1536
#define NHEADS    12
#define HDIM      128
#define QKV_N     (3 * EMBED)         // 4608
#define K3        (3 * EMBED)         // tripled K for split-bf16 GEMM = 4608
#define D2        (HDIM / 2)          // 64
#define EPS       1e-5f
#define ATT_SCALE 0.08838834764831843f   // 1/sqrt(128)

// ---------------- scratch (device globals; no runtime allocation) ----------------
__device__ float g_qkv[SEQ * QKV_N];                    // [s][3E] fp32
__device__ float g_ctx[SEQ * EMBED];                    // [s][h*d]
__device__ __nv_bfloat16 g_Ax   [SEQ * K3];             // split A for QKV gemm
__device__ __nv_bfloat16 g_Actx [SEQ * K3];             // split A for proj gemm
__device__ __nv_bfloat16 g_Wtqkv[QKV_N * K3];           // W_qkv^T split  (N x 3K)
__device__ __nv_bfloat16 g_Wtprj[EMBED * K3];           // W_proj^T split (N x 3K)
// attention operands, split hi/lo bf16, layout [h][s][d]
__device__ __nv_bfloat16 g_qh[NHEADS * SEQ * HDIM];
__device__ __nv_bfloat16 g_ql[NHEADS * SEQ * HDIM];
__device__ __nv_bfloat16 g_kh[NHEADS * SEQ * HDIM];
__device__ __nv_bfloat16 g_kl[NHEADS * SEQ * HDIM];
__device__ __nv_bfloat16 g_vh[NHEADS * SEQ * HDIM];
__device__ __nv_bfloat16 g_vl[NHEADS * SEQ * HDIM];

// ============================================================================
// helpers (sm_100-legal PTX only: mma.sync / ldmatrix / cp.async)
// ============================================================================
__device__ __forceinline__ uint32_t smem_to_u32(const void* p) {
    uint32_t a;
    asm("{ .reg .u64 t; cvta.to.shared.u64 t, %1; cvt.u32.u64 %0, t; }" : "=r"(a) : "l"(p));
    return a;
}
#define CP_ASYNC16(saddr, gptr) \
    asm volatile("cp.async.cg.shared.global [%0], [%1], 16;" \
        :: "r"(saddr), "l"(gptr) : "memory")
#define CP_COMMIT() asm volatile("cp.async.commit_group;" ::: "memory")
#define CP_WAIT0()  asm volatile("cp.async.wait_group 0;" ::: "memory")
#define CP_WAIT1()  asm volatile("cp.async.wait_group 1;" ::: "memory")

__device__ __forceinline__ void ldm_x4(uint32_t* r, uint32_t addr) {
    asm volatile("ldmatrix.sync.aligned.m8n8.x4.shared.b16 {%0,%1,%2,%3}, [%4];"
        : "=r"(r[0]), "=r"(r[1]), "=r"(r[2]), "=r"(r[3]) : "r"(addr));
}
__device__ __forceinline__ void ldm_x4_trans(uint32_t* r, uint32_t addr) {
    asm volatile("ldmatrix.sync.aligned.m8n8.x4.trans.shared.b16 {%0,%1,%2,%3}, [%4];"
        : "=r"(r[0]), "=r"(r[1]), "=r"(r[2]), "=r"(r[3]) : "r"(addr));
}
__device__ __forceinline__ void ldm_x2(uint32_t* r, uint32_t addr) {
    asm volatile("ldmatrix.sync.aligned.m8n8.x2.shared.b16 {%0,%1}, [%2];"
        : "=r"(r[0]), "=r"(r[1]) : "r"(addr));
}
__device__ __forceinline__ void mma_bf16(float* d, const uint32_t* a, const uint32_t* b) {
    asm volatile(
        "mma.sync.aligned.m16n8k16.row.col.f32.bf16.bf16.f32 "
        "{%0,%1,%2,%3}, {%4,%5,%6,%7}, {%8,%9}, {%0,%1,%2,%3};"
        : "+f"(d[0]), "+f"(d[1]), "+f"(d[2]), "+f"(d[3])
        : "r"(a[0]), "r"(a[1]), "r"(a[2]), "r"(a[3]), "r"(b[0]), "r"(b[1]));
}
__device__ __forceinline__ uint32_t pack2bf(float lo, float hi) {
    __nv_bfloat162 t = __floats2bfloat162_rn(lo, hi);
    return *(uint32_t*)&t;
}

// ============================================================================
// Split-bf16 conversion kernels
// ============================================================================
__global__ __launch_bounds__(256) void conv_split_A(
    const float* __restrict__ src, __nv_bfloat16* __restrict__ dst, int M, int K)
{
    int idx = blockIdx.x * 256 + threadIdx.x;
    if (idx >= M * K) return;
    int m = idx / K, k = idx - m * K;
    float x  = src[idx];
    __nv_bfloat16 hi = __float2bfloat16(x);
    __nv_bfloat16 lo = __float2bfloat16(x - __bfloat162float(hi));
    __nv_bfloat16* row = dst + (size_t)m * (3 * K);
    row[k]         = hi;
    row[K + k]     = lo;
    row[2 * K + k] = hi;
}

__global__ __launch_bounds__(256) void conv_split_Wt(
    const float* __restrict__ W, __nv_bfloat16* __restrict__ Wt, int K, int N)
{
    __shared__ float tile[32][33];
    int k0 = blockIdx.x * 32, n0 = blockIdx.y * 32;
    int tx = threadIdx.x, ty = threadIdx.y;   // block (32, 8)
#pragma unroll
    for (int r = 0; r < 32; r += 8)
        tile[ty + r][tx] = W[(size_t)(k0 + ty + r) * N + n0 + tx];
    __syncthreads();
#pragma unroll
    for (int r = 0; r < 32; r += 8) {
        int n = n0 + ty + r, k = k0 + tx;
        float x  = tile[tx][ty + r];
        __nv_bfloat16 hi = __float2bfloat16(x);
        __nv_bfloat16 lo = __float2bfloat16(x - __bfloat162float(hi));
        __nv_bfloat16* row = Wt + (size_t)n * (3 * K);
        row[k]         = hi;
        row[K + k]     = hi;
        row[2 * K + k] = lo;
    }
}

// ============================================================================
// mma.sync GEMM (unchanged from R4): C[M,N] = A[M,k3] @ Bt[N,k3]^T + bias[N]
// ============================================================================
#define MM_BM  128
#define MM_BN  128
#define MM_BK  32
#define MM_PAD 40

__global__ __launch_bounds__(256) void gemm_mma(
    const __nv_bfloat16* __restrict__ A, const __nv_bfloat16* __restrict__ Bt,
    const float* __restrict__ bias, float* __restrict__ C, int N, int k3)
{
    __shared__ __nv_bfloat16 As[2][MM_BM * MM_PAD];
    __shared__ __nv_bfloat16 Bs[2][MM_BN * MM_PAD];

    const int tid    = threadIdx.x;
    const int lane   = tid & 31;
    const int wid    = tid >> 5;
    const int warp_m = wid & 3;
    const int warp_n = wid >> 2;
    const int m0 = blockIdx.y * MM_BM;
    const int n0 = blockIdx.x * MM_BN;
    const int nchunk = k3 / MM_BK;

    const int ldr = tid >> 2;
    const int lds = (tid & 3) * 8;
    const __nv_bfloat16* aG = A  + (size_t)(m0 + ldr) * k3 + lds;
    const __nv_bfloat16* bG = Bt + (size_t)(n0 + ldr) * k3 + lds;
    const uint32_t As_u = smem_to_u32(&As[0][0]);
    const uint32_t Bs_u = smem_to_u32(&Bs[0][0]);
    const uint32_t aS = As_u + (uint32_t)(ldr * MM_PAD + lds) * 2;
    const uint32_t bS = Bs_u + (uint32_t)(ldr * MM_PAD + lds) * 2;
    const uint32_t bufStrideA = MM_BM * MM_PAD * 2;
    const uint32_t bufStrideB = MM_BN * MM_PAD * 2;
    const uint32_t rowHalf = 64 * MM_PAD * 2;

    float acc[2][8][4];
#pragma unroll
    for (int mt = 0; mt < 2; mt++)
#pragma unroll
        for (int nt = 0; nt < 8; nt++)
#pragma unroll
            for (int q = 0; q < 4; q++) acc[mt][nt][q] = 0.f;

    uint32_t aAddr[2], bAddr[8];
#pragma unroll
    for (int mt = 0; mt < 2; mt++) {
        int r = warp_m * 32 + mt * 16 + (lane & 15);
        int c = (lane >> 4) * 8;
        aAddr[mt] = As_u + (uint32_t)(r * MM_PAD + c) * 2;
    }
#pragma unroll
    for (int nt = 0; nt < 8; nt++) {
        int r = warp_n * 64 + nt * 8 + (lane & 7);
        int c = ((lane >> 3) & 1) * 8;
        bAddr[nt] = Bs_u + (uint32_t)(r * MM_PAD + c) * 2;
    }

    CP_ASYNC16(aS,            aG);
    CP_ASYNC16(aS + rowHalf,  aG + (size_t)64 * k3);
    CP_ASYNC16(bS,            bG);
    CP_ASYNC16(bS + rowHalf,  bG + (size_t)64 * k3);
    CP_COMMIT();

    for (int c = 0; c < nchunk; ++c) {
        const int buf = c & 1;
        if (c + 1 < nchunk) {
            const int nb = buf ^ 1;
            const __nv_bfloat16* ag = aG + (c + 1) * MM_BK;
            const __nv_bfloat16* bg = bG + (c + 1) * MM_BK;
            CP_ASYNC16(aS + nb * bufStrideA,            ag);
            CP_ASYNC16(aS + nb * bufStrideA + rowHalf,  ag + (size_t)64 * k3);
            CP_ASYNC16(bS + nb * bufStrideB,            bg);
            CP_ASYNC16(bS + nb * bufStrideB + rowHalf,  bg + (size_t)64 * k3);
            CP_COMMIT();
            CP_WAIT1();
        } else {
            CP_WAIT0();
        }
        __syncthreads();

        const uint32_t aOff = buf * bufStrideA;
        const uint32_t bOff = buf * bufStrideB;
#pragma unroll
        for (int ks = 0; ks < 2; ++ks) {
            uint32_t af[2][4], bf[8][2];
#pragma unroll
            for (int mt = 0; mt < 2; mt++) ldm_x4(af[mt], aAddr[mt] + aOff + ks * 32);
#pragma unroll
            for (int nt = 0; nt < 8; nt++) ldm_x2(bf[nt], bAddr[nt] + bOff + ks * 32);
#pragma unroll
            for (int mt = 0; mt < 2; mt++)
#pragma unroll
                for (int nt = 0; nt < 8; nt++)
                    mma_bf16(acc[mt][nt], af[mt], bf[nt]);
        }
        __syncthreads();
    }

    const int erow = lane >> 2;
    const int ecol = (lane & 3) * 2;
#pragma unroll
    for (int mt = 0; mt < 2; mt++) {
        int row = m0 + warp_m * 32 + mt * 16 + erow;
#pragma unroll
        for (int nt = 0; nt < 8; nt++) {
            int col = n0 + warp_n * 64 + nt * 8 + ecol;
            float b0 = bias[col], b1 = bias[col + 1];
            float* c0 = C + (size_t)row * N + col;
            float* c1 = C + (size_t)(row + 8) * N + col;
            c0[0] = acc[mt][nt][0] + b0;
            c0[1] = acc[mt][nt][1] + b1;
            c1[0] = acc[mt][nt][2] + b0;
            c1[1] = acc[mt][nt][3] + b1;
        }
    }
}

// ============================================================================
// RMSNorm + RoPE + split into hi/lo bf16, layout [h][s][d]
// ============================================================================
__global__ __launch_bounds__(128) void norm_rope_split(
    const float* __restrict__ cosb, const float* __restrict__ sinb,
    const float* __restrict__ qw,   const float* __restrict__ kw)
{
    const int s = blockIdx.x, h = blockIdx.y, d = threadIdx.x;
    __shared__ float sh[128];
    __shared__ float wsum[4];
    __shared__ float rms_sh;

    const float* base = g_qkv + (size_t)s * QKV_N + h * HDIM;
    const int d2 = (d < D2) ? d : d - D2;
    const float c  = cosb[s * D2 + d2];
    const float sn = sinb[s * D2 + d2];
    const size_t oidx = ((size_t)h * SEQ + s) * HDIM + d;

#pragma unroll
    for (int which = 0; which < 2; which++) {
        const float x = base[which * EMBED + d];
        float v = x * x;
#pragma unroll
        for (int o = 16; o; o >>= 1) v += __shfl_xor_sync(0xffffffffu, v, o);
        if ((d & 31) == 0) wsum[d >> 5] = v;
        __syncthreads();
        if (d == 0)
            rms_sh = rsqrtf((wsum[0] + wsum[1] + wsum[2] + wsum[3]) * (1.0f / HDIM) + EPS);
        __syncthreads();
        const float* w = which ? kw : qw;
        sh[d] = x * rms_sh * w[d];
        __syncthreads();
        float out;
        if (d < D2) out = sh[d] * c - sh[d + D2] * sn;
        else        out = sh[d] * c + sh[d - D2] * sn;
        __nv_bfloat16 hi = __float2bfloat16(out);
        __nv_bfloat16 lo = __float2bfloat16(out - __bfloat162float(hi));
        if (which == 0) { g_qh[oidx] = hi; g_ql[oidx] = lo; }
        else            { g_kh[oidx] = hi; g_kl[oidx] = lo; }
        __syncthreads();
    }
    float v = base[2 * EMBED + d];
    __nv_bfloat16 vh = __float2bfloat16(v);
    g_vh[oidx] = vh;
    g_vl[oidx] = __float2bfloat16(v - __bfloat162float(vh));
}

// ============================================================================
// tensor-core flash attention
// CTA = (64 queries, 1 head); 4 warps x 16 rows; BK=64 keys.
// smem: Qh Ql Kh Kl Vh Vl tiles, 64 rows x 128 cols bf16, row stride 136.
// ============================================================================
#define AT_PADE 136                       // bf16 elements per smem row
#define AT_ROWB (AT_PADE * 2)             // 272 bytes
#define AT_TILE (64 * AT_PADE)            // elements per tile
#define AT_SMEM_B (6 * AT_TILE * 2)       // 104448 bytes

__global__ __launch_bounds__(128) void attn_mma(const int* __restrict__ cu, int ncu)
{
    extern __shared__ __nv_bfloat16 asm_smem[];
    const uint32_t S_u  = smem_to_u32(asm_smem);
    const uint32_t QH_u = S_u;
    const uint32_t QL_u = S_u + 1 * AT_TILE * 2;
    const uint32_t KH_u = S_u + 2 * AT_TILE * 2;
    const uint32_t KL_u = S_u + 3 * AT_TILE * 2;
    const uint32_t VH_u = S_u + 4 * AT_TILE * 2;
    const uint32_t VL_u = S_u + 5 * AT_TILE * 2;
    __shared__ int scu[16];

    const int h    = blockIdx.y;
    const int q0   = blockIdx.x * 64;
    const int tid  = threadIdx.x;
    const int warp = tid >> 5;
    const int lane = tid & 31;

    const size_t hb = (size_t)h * SEQ * HDIM;

    // ---- issue Q tile loads (once per CTA)
#pragma unroll
    for (int c = 0; c < 8; c++) {
        int i = c * 128 + tid;
        int row = i >> 4, ch = (i & 15) * 16;
        const char* s1 = (const char*)(g_qh + hb + (size_t)(q0 + row) * HDIM) + ch;
        const char* s2 = (const char*)(g_ql + hb + (size_t)(q0 + row) * HDIM) + ch;
        CP_ASYNC16(QH_u + row * AT_ROWB + ch, s1);
        CP_ASYNC16(QL_u + row * AT_ROWB + ch, s2);
    }
    CP_COMMIT();

    if (tid < ncu && tid < 16) scu[tid] = cu[tid];
    __syncthreads();

    // segment of position p: count of cu[i] <= p for i in [1, ncu)
    auto seg = [&](int p) {
        int sgi = 0;
        for (int i = 1; i < ncu; i++) sgi += (scu[i] <= p) ? 1 : 0;
        return sgi;
    };
    int klo, khi;
    {
        int s0 = seg(q0), s1 = seg(q0 + 63);
        if (s0 == s1) { klo = scu[s0]; khi = scu[s0 + 1]; }
        else          { klo = 0;       khi = SEQ; }
    }
    const int rloc  = lane >> 2;                 // 0..7
    const int r0g   = q0 + warp * 16 + rloc;     // global row of c0/c1
    const int r1g   = r0g + 8;                   // global row of c2/c3
    const int sq0   = seg(r0g), sq1 = seg(r1g);

    // per-warp softmax state (rows owned entirely by this warp)
    float m0 = -1e30f, m1 = -1e30f, l0 = 0.f, l1 = 0.f;
    float o[16][4];
#pragma unroll
    for (int nt = 0; nt < 16; nt++)
#pragma unroll
        for (int q = 0; q < 4; q++) o[nt][q] = 0.f;

    // fragment address bases
    const uint32_t aoff = (uint32_t)((warp * 16 + (lane & 15)) * AT_ROWB + ((lane >> 4) * 8) * 2);
    const uint32_t boff = (uint32_t)(((lane & 7) + ((lane >> 4) << 3)) * AT_ROWB + (((lane >> 3) & 1) * 8) * 2);
    const uint32_t voff = (uint32_t)((((lane >> 3) & 1) * 8 + (lane & 7)) * AT_ROWB + ((lane >> 4) * 8) * 2);

    for (int kb = klo; kb < khi; kb += 64) {
        __syncthreads();   // protect smem from previous iteration's consumers
        // ---- load K/V tiles (rows clamped; out-of-range keys masked later)
#pragma unroll
        for (int c = 0; c < 8; c++) {
            int i = c * 128 + tid;
            int row = i >> 4, ch = (i & 15) * 16;
            int gr = kb + row; if (gr > khi - 1) gr = khi - 1;
            const char* p1 = (const char*)(g_kh + hb + (size_t)gr * HDIM) + ch;
            const char* p2 = (const char*)(g_kl + hb + (size_t)gr * HDIM) + ch;
            const char* p3 = (const char*)(g_vh + hb + (size_t)gr * HDIM) + ch;
            const char* p4 = (const char*)(g_vl + hb + (size_t)gr * HDIM) + ch;
            uint32_t db = (uint32_t)(row * AT_ROWB + ch);
            CP_ASYNC16(KH_u + db, p1);
            CP_ASYNC16(KL_u + db, p2);
            CP_ASYNC16(VH_u + db, p3);
            CP_ASYNC16(VL_u + db, p4);
        }
        CP_COMMIT();
        CP_WAIT0();
        __syncthreads();

        // ---- S = scale * (Qh Kh^T + Ql Kh^T + Qh Kl^T)
        float s[8][4];
#pragma unroll
        for (int nt = 0; nt < 8; nt++)
#pragma unroll
            for (int q = 0; q < 4; q++) s[nt][q] = 0.f;

        const uint32_t aB[3] = { QH_u, QL_u, QH_u };
        const uint32_t bB[3] = { KH_u, KH_u, KL_u };
#pragma unroll
        for (int pass = 0; pass < 3; pass++) {
#pragma unroll
            for (int ks = 0; ks < 8; ks++) {
                uint32_t af[4];
                ldm_x4(af, aB[pass] + aoff + ks * 32);
#pragma unroll
                for (int np = 0; np < 4; np++) {
                    uint32_t bf[4];
                    ldm_x4(bf, bB[pass] + boff + np * 16 * AT_ROWB + ks * 32);
                    mma_bf16(s[2 * np],     af, bf);
                    mma_bf16(s[2 * np + 1], af, bf + 2);
                }
            }
        }

        // ---- scale + segment mask
#pragma unroll
        for (int nt = 0; nt < 8; nt++) {
            int j0 = kb + nt * 8 + (lane & 3) * 2;
            int j1 = j0 + 1;
            int sk0 = (j0 < khi) ? seg(j0) : -1;
            int sk1 = (j1 < khi) ? seg(j1) : -1;
            s[nt][0] = (sk0 == sq0) ? s[nt][0] * ATT_SCALE : -1e30f;
            s[nt][1] = (sk1 == sq0) ? s[nt][1] * ATT_SCALE : -1e30f;
            s[nt][2] = (sk0 == sq1) ? s[nt][2] * ATT_SCALE : -1e30f;
            s[nt][3] = (sk1 == sq1) ? s[nt][3] * ATT_SCALE : -1e30f;
        }

        // ---- online softmax (rows warp-local; 4 lanes share a row)
        float mx0 = -1e30f, mx1 = -1e30f;
#pragma unroll
        for (int nt = 0; nt < 8; nt++) {
            mx0 = fmaxf(mx0, fmaxf(s[nt][0], s[nt][1]));
            mx1 = fmaxf(mx1, fmaxf(s[nt][2], s[nt][3]));
        }
        mx0 = fmaxf(mx0, __shfl_xor_sync(0xffffffffu, mx0, 1));
        mx0 = fmaxf(mx0, __shfl_xor_sync(0xffffffffu, mx0, 2));
        mx1 = fmaxf(mx1, __shfl_xor_sync(0xffffffffu, mx1, 1));
        mx1 = fmaxf(mx1, __shfl_xor_sync(0xffffffffu, mx1, 2));
        float mn0 = fmaxf(m0, mx0), mn1 = fmaxf(m1, mx1);
        bool live0 = mn0 > -1e29f, live1 = mn1 > -1e29f;
        float a0 = live0 ? __expf(m0 - mn0) : 1.f;
        float a1 = live1 ? __expf(m1 - mn1) : 1.f;
        float ls0 = 0.f, ls1 = 0.f;
#pragma unroll
        for (int nt = 0; nt < 8; nt++) {
            float p0 = live0 ? __expf(s[nt][0] - mn0) : 0.f;
            float p1 = live0 ? __expf(s[nt][1] - mn0) : 0.f;
            float p2 = live1 ? __expf(s[nt][2] - mn1) : 0.f;
            float p3 = live1 ? __expf(s[nt][3] - mn1) : 0.f;
            s[nt][0] = p0; s[nt][1] = p1; s[nt][2] = p2; s[nt][3] = p3;
            ls0 += p0 + p1; ls1 += p2 + p3;
        }
        ls0 += __shfl_xor_sync(0xffffffffu, ls0, 1);
        ls0 += __shfl_xor_sync(0xffffffffu, ls0, 2);
        ls1 += __shfl_xor_sync(0xffffffffu, ls1, 1);
        ls1 += __shfl_xor_sync(0xffffffffu, ls1, 2);
        l0 = l0 * a0 + ls0;  l1 = l1 * a1 + ls1;
        m0 = mn0;  m1 = mn1;

        // rescale O
#pragma unroll
        for (int nt = 0; nt < 16; nt++) {
            o[nt][0] *= a0; o[nt][1] *= a0;
            o[nt][2] *= a1; o[nt][3] *= a1;
        }

        // ---- O += Ph Vh + Pl Vh + Ph Vl   (P repacked from S fragments)
#pragma unroll
        for (int js = 0; js < 4; js++) {
            float* t0 = s[2 * js];
            float* t1 = s[2 * js + 1];
            uint32_t ph[4], pl[4];
            ph[0] = pack2bf(t0[0], t0[1]);
            ph[1] = pack2bf(t0[2], t0[3]);
            ph[2] = pack2bf(t1[0], t1[1]);
            ph[3] = pack2bf(t1[2], t1[3]);
            float r00 = t0[0] - __bfloat162float(__float2bfloat16(t0[0]));
            float r01 = t0[1] - __bfloat162float(__float2bfloat16(t0[1]));
            float r02 = t0[2] - __bfloat162float(__float2bfloat16(t0[2]));
            float r03 = t0[3] - __bfloat162float(__float2bfloat16(t0[3]));
            float r10 = t1[0] - __bfloat162float(__float2bfloat16(t1[0]));
            float r11 = t1[1] - __bfloat162float(__float2bfloat16(t1[1]));
            float r12 = t1[2] - __bfloat162float(__float2bfloat16(t1[2]));
            float r13 = t1[3] - __bfloat162float(__float2bfloat16(t1[3]));
            pl[0] = pack2bf(r00, r01);
            pl[1] = pack2bf(r02, r03);
            pl[2] = pack2bf(r10, r11);
            pl[3] = pack2bf(r12, r13);

            uint32_t vbase = (uint32_t)(js * 16 * AT_ROWB) + voff;
#pragma unroll
            for (int dp = 0; dp < 8; dp++) {
                uint32_t vh4[4], vl4[4];
                ldm_x4_trans(vh4, VH_u + vbase + dp * 32);
                mma_bf16(o[2 * dp],     ph, vh4);
                mma_bf16(o[2 * dp + 1], ph, vh4 + 2);
                mma_bf16(o[2 * dp],     pl, vh4);
                mma_bf16(o[2 * dp + 1], pl, vh4 + 2);
                ldm_x4_trans(vl4, VL_u + vbase + dp * 32);
                mma_bf16(o[2 * dp],     ph, vl4);
                mma_bf16(o[2 * dp + 1], ph, vl4 + 2);
            }
        }
    }

    // ---- epilogue
    float inv0 = 1.0f / fmaxf(l0, 1e-30f);
    float inv1 = 1.0f / fmaxf(l1, 1e-30f);
    const int cb = h * HDIM + (lane & 3) * 2;
#pragma unroll
    for (int nt = 0; nt < 16; nt++) {
        float2 w0 = make_float2(o[nt][0] * inv0, o[nt][1] * inv0);
        float2 w1 = make_float2(o[nt][2] * inv1, o[nt][3] * inv1);
        *(float2*)(g_ctx + (size_t)r0g * EMBED + cb + nt * 8) = w0;
        *(float2*)(g_ctx + (size_t)r1g * EMBED + cb + nt * 8) = w1;
    }
}

// ============================================================================
// launch
// ============================================================================
extern "C" void kernel_launch(void* const* d_in, const int* in_sizes, int n_in,
                              void* d_out, int out_size)
{
    const float* x      = (const float*)d_in[0];
    const int*   cu     = (const int*)  d_in[1];
    const float* cosb   = (const float*)d_in[2];
    const float* sinb   = (const float*)d_in[3];
    const float* w_qkv  = (const float*)d_in[4];
    const float* b_qkv  = (const float*)d_in[5];
    const float* qw     = (const float*)d_in[6];
    const float* kw     = (const float*)d_in[7];
    const float* w_proj = (const float*)d_in[8];
    const float* b_proj = (const float*)d_in[9];
    float* out = (float*)d_out;
    const int ncu = in_sizes[1];

    float *qkv_p, *ctx_p;
    __nv_bfloat16 *Ax_p, *Actx_p, *Wtqkv_p, *Wtprj_p;
    cudaGetSymbolAddress((void**)&qkv_p,   g_qkv);
    cudaGetSymbolAddress((void**)&ctx_p,   g_ctx);
    cudaGetSymbolAddress((void**)&Ax_p,    g_Ax);
    cudaGetSymbolAddress((void**)&Actx_p,  g_Actx);
    cudaGetSymbolAddress((void**)&Wtqkv_p, g_Wtqkv);
    cudaGetSymbolAddress((void**)&Wtprj_p, g_Wtprj);

    cudaFuncSetAttribute(attn_mma, cudaFuncAttributeMaxDynamicSharedMemorySize, AT_SMEM_B);

    // split conversions
    conv_split_A<<<(SEQ * EMBED + 255) / 256, 256>>>(x, Ax_p, SEQ, EMBED);
    conv_split_Wt<<<dim3(EMBED / 32, QKV_N / 32), dim3(32, 8)>>>(w_qkv, Wtqkv_p, EMBED, QKV_N);
    conv_split_Wt<<<dim3(EMBED / 32, EMBED / 32), dim3(32, 8)>>>(w_proj, Wtprj_p, EMBED, EMBED);

    // 1) QKV = x @ w_qkv + b_qkv   (HMMA bf16 split)
    gemm_mma<<<dim3(QKV_N / MM_BN, SEQ / MM_BM), 256>>>(Ax_p, Wtqkv_p, b_qkv, qkv_p, QKV_N, K3);

    // 2) RMSNorm + RoPE + hi/lo split
    norm_rope_split<<<dim3(SEQ, NHEADS), 128>>>(cosb, sinb, qw, kw);

    // 3) tensor-core flash attention
    attn_mma<<<dim3(SEQ / 64, NHEADS), 128, AT_SMEM_B>>>(cu, ncu);

    // 4) out = ctx @ w_proj + b_proj   (HMMA bf16 split)
    conv_split_A<<<(SEQ * EMBED + 255) / 256, 256>>>(ctx_p, Actx_p, SEQ, EMBED);
    gemm_mma<<<dim3(EMBED / MM_BN, SEQ / MM_BM), 256>>>(Actx_p, Wtprj_p, b_proj, out, EMBED, K3);
}

// round 6
// speedup vs baseline: 3.6819x; 1.1578x over previous
#include <cuda_runtime.h>
#include <cuda_bf16.h>
#include <math.h>
#include <stdint.h>

#define SEQ       2048
#define EMBED     1536
#define NHEADS    12
#define HDIM      128
#define QKV_N     (3 * EMBED)         // 4608
#define K3        (3 * EMBED)         // tripled K for split-bf16 GEMM = 4608
#define D2        (HDIM / 2)          // 64
#define EPS       1e-5f
#define ATT_SCALE 0.08838834764831843f   // 1/sqrt(128)

// ---------------- scratch (device globals; no runtime allocation) ----------------
__device__ float g_qkv[SEQ * QKV_N];                    // [s][3E] fp32
__device__ float g_ctx[SEQ * EMBED];                    // [s][h*d]
__device__ __nv_bfloat16 g_Ax   [SEQ * K3];             // split A for QKV gemm
__device__ __nv_bfloat16 g_Actx [SEQ * K3];             // split A for proj gemm
__device__ __nv_bfloat16 g_Wtqkv[QKV_N * K3];           // W_qkv^T split  (N x 3K)
__device__ __nv_bfloat16 g_Wtprj[EMBED * K3];           // W_proj^T split (N x 3K)
// attention operands, split hi/lo bf16, layout [h][s][d]
__device__ __nv_bfloat16 g_qh[NHEADS * SEQ * HDIM];
__device__ __nv_bfloat16 g_ql[NHEADS * SEQ * HDIM];
__device__ __nv_bfloat16 g_kh[NHEADS * SEQ * HDIM];
__device__ __nv_bfloat16 g_kl[NHEADS * SEQ * HDIM];
__device__ __nv_bfloat16 g_vh[NHEADS * SEQ * HDIM];
__device__ __nv_bfloat16 g_vl[NHEADS * SEQ * HDIM];

// ============================================================================
// helpers (sm_100-legal PTX only)
// ============================================================================
__device__ __forceinline__ uint32_t smem_to_u32(const void* p) {
    uint32_t a;
    asm("{ .reg .u64 t; cvta.to.shared.u64 t, %1; cvt.u32.u64 %0, t; }" : "=r"(a) : "l"(p));
    return a;
}
#define CP_ASYNC16(saddr, gptr) \
    asm volatile("cp.async.cg.shared.global [%0], [%1], 16;" \
        :: "r"(saddr), "l"(gptr) : "memory")
#define CP_COMMIT() asm volatile("cp.async.commit_group;" ::: "memory")
#define CP_WAIT0()  asm volatile("cp.async.wait_group 0;" ::: "memory")
#define CP_WAIT1()  asm volatile("cp.async.wait_group 1;" ::: "memory")

__device__ __forceinline__ void ldm_x4(uint32_t* r, uint32_t addr) {
    asm volatile("ldmatrix.sync.aligned.m8n8.x4.shared.b16 {%0,%1,%2,%3}, [%4];"
        : "=r"(r[0]), "=r"(r[1]), "=r"(r[2]), "=r"(r[3]) : "r"(addr));
}
__device__ __forceinline__ void ldm_x4_trans(uint32_t* r, uint32_t addr) {
    asm volatile("ldmatrix.sync.aligned.m8n8.x4.trans.shared.b16 {%0,%1,%2,%3}, [%4];"
        : "=r"(r[0]), "=r"(r[1]), "=r"(r[2]), "=r"(r[3]) : "r"(addr));
}
__device__ __forceinline__ void mma_bf16(float* d, const uint32_t* a, const uint32_t* b) {
    asm volatile(
        "mma.sync.aligned.m16n8k16.row.col.f32.bf16.bf16.f32 "
        "{%0,%1,%2,%3}, {%4,%5,%6,%7}, {%8,%9}, {%0,%1,%2,%3};"
        : "+f"(d[0]), "+f"(d[1]), "+f"(d[2]), "+f"(d[3])
        : "r"(a[0]), "r"(a[1]), "r"(a[2]), "r"(a[3]), "r"(b[0]), "r"(b[1]));
}
__device__ __forceinline__ uint32_t pack2bf(float lo, float hi) {
    __nv_bfloat162 t = __floats2bfloat162_rn(lo, hi);
    return *(uint32_t*)&t;
}

// ============================================================================
// Split-bf16 conversion kernels
// ============================================================================
__global__ __launch_bounds__(256) void conv_split_A(
    const float* __restrict__ src, __nv_bfloat16* __restrict__ dst, int M, int K)
{
    int idx = blockIdx.x * 256 + threadIdx.x;
    if (idx >= M * K) return;
    int m = idx / K, k = idx - m * K;
    float x  = src[idx];
    __nv_bfloat16 hi = __float2bfloat16(x);
    __nv_bfloat16 lo = __float2bfloat16(x - __bfloat162float(hi));
    __nv_bfloat16* row = dst + (size_t)m * (3 * K);
    row[k]         = hi;
    row[K + k]     = lo;
    row[2 * K + k] = hi;
}

__global__ __launch_bounds__(256) void conv_split_Wt(
    const float* __restrict__ W, __nv_bfloat16* __restrict__ Wt, int K, int N)
{
    __shared__ float tile[32][33];
    int k0 = blockIdx.x * 32, n0 = blockIdx.y * 32;
    int tx = threadIdx.x, ty = threadIdx.y;   // block (32, 8)
#pragma unroll
    for (int r = 0; r < 32; r += 8)
        tile[ty + r][tx] = W[(size_t)(k0 + ty + r) * N + n0 + tx];
    __syncthreads();
#pragma unroll
    for (int r = 0; r < 32; r += 8) {
        int n = n0 + ty + r, k = k0 + tx;
        float x  = tile[tx][ty + r];
        __nv_bfloat16 hi = __float2bfloat16(x);
        __nv_bfloat16 lo = __float2bfloat16(x - __bfloat162float(hi));
        __nv_bfloat16* row = Wt + (size_t)n * (3 * K);
        row[k]         = hi;
        row[K + k]     = hi;
        row[2 * K + k] = lo;
    }
}

// ============================================================================
// mma.sync GEMM v3: C[M,N] = A[M,k3] @ Bt[N,k3]^T + bias[N]
// CTA 128x128, BK=64, 3-stage cp.async ring, 1 syncthreads per chunk.
// ============================================================================
#define MM_BM     128
#define MM_BN     128
#define MM_BK     64
#define MM_PADB   144                        // bytes per smem row (128 data + 16 pad)
#define MM_TILEB  (128 * MM_PADB)            // 18432 B per matrix per stage
#define MM_STAGEB (2 * MM_TILEB)             // 36864
#define MM_STAGES 3
#define MM_SMEM   (MM_STAGES * MM_STAGEB)    // 110592

__device__ __forceinline__ void mm_load_tile(
    const __nv_bfloat16* __restrict__ src, int row0, int k3, int chunk,
    uint32_t dstBase, int tid)
{
#pragma unroll
    for (int c2 = 0; c2 < 4; c2++) {
        int idx = c2 * 256 + tid;
        int row = idx >> 3;
        int col = (idx & 7) * 16;
        const char* g = (const char*)(src + (size_t)(row0 + row) * k3) + chunk * 128 + col;
        CP_ASYNC16(dstBase + (uint32_t)(row * MM_PADB + col), g);
    }
}

__global__ __launch_bounds__(256) void gemm_mma(
    const __nv_bfloat16* __restrict__ A, const __nv_bfloat16* __restrict__ Bt,
    const float* __restrict__ bias, float* __restrict__ C, int N, int k3)
{
    extern __shared__ char mmsm[];
    const uint32_t S_u = smem_to_u32(mmsm);

    const int tid    = threadIdx.x;
    const int lane   = tid & 31;
    const int wid    = tid >> 5;
    const int warp_m = wid & 3;
    const int warp_n = wid >> 2;
    const int m0 = blockIdx.y * MM_BM;
    const int n0 = blockIdx.x * MM_BN;
    const int nchunk = k3 / MM_BK;   // 72

    float acc[2][8][4];
#pragma unroll
    for (int mt = 0; mt < 2; mt++)
#pragma unroll
        for (int nt = 0; nt < 8; nt++)
#pragma unroll
            for (int q = 0; q < 4; q++) acc[mt][nt][q] = 0.f;

    // fragment byte offsets within a stage's A/B tile
    const uint32_t aFrag = (uint32_t)((warp_m * 32 + (lane & 15)) * MM_PADB + (lane >> 4) * 16);
    const uint32_t bFrag = (uint32_t)((warp_n * 64 + ((lane >> 4) << 3) + (lane & 7)) * MM_PADB
                                      + ((lane >> 3) & 1) * 16);

    // prologue: load chunks 0,1 into stages 0,1
    mm_load_tile(A,  m0, k3, 0, S_u,             tid);
    mm_load_tile(Bt, n0, k3, 0, S_u + MM_TILEB,  tid);
    CP_COMMIT();
    mm_load_tile(A,  m0, k3, 1, S_u + MM_STAGEB,            tid);
    mm_load_tile(Bt, n0, k3, 1, S_u + MM_STAGEB + MM_TILEB, tid);
    CP_COMMIT();

    int slot = 0;
    for (int c = 0; c < nchunk; ++c) {
        CP_WAIT1();          // chunk c resident
        __syncthreads();     // visible to all warps; slot (c+2)%3 free
        if (c + 2 < nchunk) {
            int ns = (slot + 2) % MM_STAGES;
            mm_load_tile(A,  m0, k3, c + 2, S_u + ns * MM_STAGEB,            tid);
            mm_load_tile(Bt, n0, k3, c + 2, S_u + ns * MM_STAGEB + MM_TILEB, tid);
        }
        CP_COMMIT();         // always commit (possibly empty) to keep group count

        const uint32_t Au = S_u + slot * MM_STAGEB;
        const uint32_t Bu = Au + MM_TILEB;
#pragma unroll
        for (int ks = 0; ks < 4; ++ks) {
            uint32_t af[2][4], bf[4][4];
            ldm_x4(af[0], Au + aFrag + ks * 32);
            ldm_x4(af[1], Au + aFrag + 16 * MM_PADB + ks * 32);
#pragma unroll
            for (int p = 0; p < 4; p++)
                ldm_x4(bf[p], Bu + bFrag + p * 16 * MM_PADB + ks * 32);
#pragma unroll
            for (int mt = 0; mt < 2; mt++)
#pragma unroll
                for (int p = 0; p < 4; p++) {
                    mma_bf16(acc[mt][2 * p],     af[mt], bf[p]);
                    mma_bf16(acc[mt][2 * p + 1], af[mt], bf[p] + 2);
                }
        }
        slot = (slot + 1) % MM_STAGES;
    }

    // ---- epilogue with bias
    const int erow = lane >> 2;
    const int ecol = (lane & 3) * 2;
#pragma unroll
    for (int mt = 0; mt < 2; mt++) {
        int row = m0 + warp_m * 32 + mt * 16 + erow;
#pragma unroll
        for (int nt = 0; nt < 8; nt++) {
            int col = n0 + warp_n * 64 + nt * 8 + ecol;
            float b0 = bias[col], b1 = bias[col + 1];
            float* c0 = C + (size_t)row * N + col;
            float* c1 = C + (size_t)(row + 8) * N + col;
            c0[0] = acc[mt][nt][0] + b0;
            c0[1] = acc[mt][nt][1] + b1;
            c1[0] = acc[mt][nt][2] + b0;
            c1[1] = acc[mt][nt][3] + b1;
        }
    }
}

// ============================================================================
// RMSNorm + RoPE + split into hi/lo bf16, layout [h][s][d]
// ============================================================================
__global__ __launch_bounds__(128) void norm_rope_split(
    const float* __restrict__ cosb, const float* __restrict__ sinb,
    const float* __restrict__ qw,   const float* __restrict__ kw)
{
    const int s = blockIdx.x, h = blockIdx.y, d = threadIdx.x;
    __shared__ float sh[128];
    __shared__ float wsum[4];
    __shared__ float rms_sh;

    const float* base = g_qkv + (size_t)s * QKV_N + h * HDIM;
    const int d2 = (d < D2) ? d : d - D2;
    const float c  = cosb[s * D2 + d2];
    const float sn = sinb[s * D2 + d2];
    const size_t oidx = ((size_t)h * SEQ + s) * HDIM + d;

#pragma unroll
    for (int which = 0; which < 2; which++) {
        const float x = base[which * EMBED + d];
        float v = x * x;
#pragma unroll
        for (int o = 16; o; o >>= 1) v += __shfl_xor_sync(0xffffffffu, v, o);
        if ((d & 31) == 0) wsum[d >> 5] = v;
        __syncthreads();
        if (d == 0)
            rms_sh = rsqrtf((wsum[0] + wsum[1] + wsum[2] + wsum[3]) * (1.0f / HDIM) + EPS);
        __syncthreads();
        const float* w = which ? kw : qw;
        sh[d] = x * rms_sh * w[d];
        __syncthreads();
        float out;
        if (d < D2) out = sh[d] * c - sh[d + D2] * sn;
        else        out = sh[d] * c + sh[d - D2] * sn;
        __nv_bfloat16 hi = __float2bfloat16(out);
        __nv_bfloat16 lo = __float2bfloat16(out - __bfloat162float(hi));
        if (which == 0) { g_qh[oidx] = hi; g_ql[oidx] = lo; }
        else            { g_kh[oidx] = hi; g_kl[oidx] = lo; }
        __syncthreads();
    }
    float v = base[2 * EMBED + d];
    __nv_bfloat16 vh = __float2bfloat16(v);
    g_vh[oidx] = vh;
    g_vl[oidx] = __float2bfloat16(v - __bfloat162float(vh));
}

// ============================================================================
// tensor-core flash attention with K/V load overlap
// CTA = (64 queries, 1 head); 4 warps x 16 rows; BK=64 keys.
// ============================================================================
#define AT_PADE 136                       // bf16 elements per smem row
#define AT_ROWB (AT_PADE * 2)             // 272 bytes
#define AT_TILE (64 * AT_PADE)            // elements per tile
#define AT_SMEM_B (6 * AT_TILE * 2)       // 104448 bytes

__global__ __launch_bounds__(128) void attn_mma(const int* __restrict__ cu, int ncu)
{
    extern __shared__ __nv_bfloat16 asm_smem[];
    const uint32_t S_u  = smem_to_u32(asm_smem);
    const uint32_t QH_u = S_u;
    const uint32_t QL_u = S_u + 1 * AT_TILE * 2;
    const uint32_t KH_u = S_u + 2 * AT_TILE * 2;
    const uint32_t KL_u = S_u + 3 * AT_TILE * 2;
    const uint32_t VH_u = S_u + 4 * AT_TILE * 2;
    const uint32_t VL_u = S_u + 5 * AT_TILE * 2;
    __shared__ int scu[16];

    const int h    = blockIdx.y;
    const int q0   = blockIdx.x * 64;
    const int tid  = threadIdx.x;
    const int warp = tid >> 5;
    const int lane = tid & 31;

    const size_t hb = (size_t)h * SEQ * HDIM;

    // loaders
    auto issueK = [&](int kb, int khi) {
#pragma unroll
        for (int c = 0; c < 8; c++) {
            int i = c * 128 + tid;
            int row = i >> 4, ch = (i & 15) * 16;
            int gr = kb + row; if (gr > khi - 1) gr = khi - 1;
            uint32_t db = (uint32_t)(row * AT_ROWB + ch);
            CP_ASYNC16(KH_u + db, (const char*)(g_kh + hb + (size_t)gr * HDIM) + ch);
            CP_ASYNC16(KL_u + db, (const char*)(g_kl + hb + (size_t)gr * HDIM) + ch);
        }
    };
    auto issueV = [&](int kb, int khi) {
#pragma unroll
        for (int c = 0; c < 8; c++) {
            int i = c * 128 + tid;
            int row = i >> 4, ch = (i & 15) * 16;
            int gr = kb + row; if (gr > khi - 1) gr = khi - 1;
            uint32_t db = (uint32_t)(row * AT_ROWB + ch);
            CP_ASYNC16(VH_u + db, (const char*)(g_vh + hb + (size_t)gr * HDIM) + ch);
            CP_ASYNC16(VL_u + db, (const char*)(g_vl + hb + (size_t)gr * HDIM) + ch);
        }
    };

    if (tid < ncu && tid < 16) scu[tid] = cu[tid];
    __syncthreads();

    auto seg = [&](int p) {
        int sgi = 0;
        for (int i = 1; i < ncu; i++) sgi += (scu[i] <= p) ? 1 : 0;
        return sgi;
    };
    int klo, khi;
    {
        int s0 = seg(q0), s1 = seg(q0 + 63);
        if (s0 == s1) { klo = scu[s0]; khi = scu[s0 + 1]; }
        else          { klo = 0;       khi = SEQ; }
    }

    // prologue: group0 = Q + K(klo), group1 = V(klo)
#pragma unroll
    for (int c = 0; c < 8; c++) {
        int i = c * 128 + tid;
        int row = i >> 4, ch = (i & 15) * 16;
        CP_ASYNC16(QH_u + row * AT_ROWB + ch, (const char*)(g_qh + hb + (size_t)(q0 + row) * HDIM) + ch);
        CP_ASYNC16(QL_u + row * AT_ROWB + ch, (const char*)(g_ql + hb + (size_t)(q0 + row) * HDIM) + ch);
    }
    issueK(klo, khi);
    CP_COMMIT();
    issueV(klo, khi);
    CP_COMMIT();

    const int rloc  = lane >> 2;
    const int r0g   = q0 + warp * 16 + rloc;
    const int r1g   = r0g + 8;
    const int sq0   = seg(r0g), sq1 = seg(r1g);

    float m0 = -1e30f, m1 = -1e30f, l0 = 0.f, l1 = 0.f;
    float o[16][4];
#pragma unroll
    for (int nt = 0; nt < 16; nt++)
#pragma unroll
        for (int q = 0; q < 4; q++) o[nt][q] = 0.f;

    const uint32_t aoff = (uint32_t)((warp * 16 + (lane & 15)) * AT_ROWB + ((lane >> 4) * 8) * 2);
    const uint32_t boff = (uint32_t)(((lane & 7) + ((lane >> 4) << 3)) * AT_ROWB + (((lane >> 3) & 1) * 8) * 2);
    const uint32_t voff = (uint32_t)((((lane >> 3) & 1) * 8 + (lane & 7)) * AT_ROWB + ((lane >> 4) * 8) * 2);

    for (int kb = klo; kb < khi; kb += 64) {
        const int knext = kb + 64;

        CP_WAIT1();          // Q + K(kb) resident
        __syncthreads();

        // ---- S = scale * (Qh Kh^T + Ql Kh^T + Qh Kl^T)
        float s[8][4];
#pragma unroll
        for (int nt = 0; nt < 8; nt++)
#pragma unroll
            for (int q = 0; q < 4; q++) s[nt][q] = 0.f;

        const uint32_t aB[3] = { QH_u, QL_u, QH_u };
        const uint32_t bB[3] = { KH_u, KH_u, KL_u };
#pragma unroll
        for (int pass = 0; pass < 3; pass++) {
#pragma unroll
            for (int ks = 0; ks < 8; ks++) {
                uint32_t af[4];
                ldm_x4(af, aB[pass] + aoff + ks * 32);
#pragma unroll
                for (int np = 0; np < 4; np++) {
                    uint32_t bf[4];
                    ldm_x4(bf, bB[pass] + boff + np * 16 * AT_ROWB + ks * 32);
                    mma_bf16(s[2 * np],     af, bf);
                    mma_bf16(s[2 * np + 1], af, bf + 2);
                }
            }
        }

        __syncthreads();                       // all warps done reading K
        if (knext < khi) issueK(knext, khi);   // overlap K load with softmax+PV
        CP_COMMIT();

        // ---- scale + segment mask
#pragma unroll
        for (int nt = 0; nt < 8; nt++) {
            int j0 = kb + nt * 8 + (lane & 3) * 2;
            int j1 = j0 + 1;
            int sk0 = (j0 < khi) ? seg(j0) : -1;
            int sk1 = (j1 < khi) ? seg(j1) : -1;
            s[nt][0] = (sk0 == sq0) ? s[nt][0] * ATT_SCALE : -1e30f;
            s[nt][1] = (sk1 == sq0) ? s[nt][1] * ATT_SCALE : -1e30f;
            s[nt][2] = (sk0 == sq1) ? s[nt][2] * ATT_SCALE : -1e30f;
            s[nt][3] = (sk1 == sq1) ? s[nt][3] * ATT_SCALE : -1e30f;
        }

        // ---- online softmax (registers only)
        float mx0 = -1e30f, mx1 = -1e30f;
#pragma unroll
        for (int nt = 0; nt < 8; nt++) {
            mx0 = fmaxf(mx0, fmaxf(s[nt][0], s[nt][1]));
            mx1 = fmaxf(mx1, fmaxf(s[nt][2], s[nt][3]));
        }
        mx0 = fmaxf(mx0, __shfl_xor_sync(0xffffffffu, mx0, 1));
        mx0 = fmaxf(mx0, __shfl_xor_sync(0xffffffffu, mx0, 2));
        mx1 = fmaxf(mx1, __shfl_xor_sync(0xffffffffu, mx1, 1));
        mx1 = fmaxf(mx1, __shfl_xor_sync(0xffffffffu, mx1, 2));
        float mn0 = fmaxf(m0, mx0), mn1 = fmaxf(m1, mx1);
        bool live0 = mn0 > -1e29f, live1 = mn1 > -1e29f;
        float a0 = live0 ? __expf(m0 - mn0) : 1.f;
        float a1 = live1 ? __expf(m1 - mn1) : 1.f;
        float ls0 = 0.f, ls1 = 0.f;
#pragma unroll
        for (int nt = 0; nt < 8; nt++) {
            float p0 = live0 ? __expf(s[nt][0] - mn0) : 0.f;
            float p1 = live0 ? __expf(s[nt][1] - mn0) : 0.f;
            float p2 = live1 ? __expf(s[nt][2] - mn1) : 0.f;
            float p3 = live1 ? __expf(s[nt][3] - mn1) : 0.f;
            s[nt][0] = p0; s[nt][1] = p1; s[nt][2] = p2; s[nt][3] = p3;
            ls0 += p0 + p1; ls1 += p2 + p3;
        }
        ls0 += __shfl_xor_sync(0xffffffffu, ls0, 1);
        ls0 += __shfl_xor_sync(0xffffffffu, ls0, 2);
        ls1 += __shfl_xor_sync(0xffffffffu, ls1, 1);
        ls1 += __shfl_xor_sync(0xffffffffu, ls1, 2);
        l0 = l0 * a0 + ls0;  l1 = l1 * a1 + ls1;
        m0 = mn0;  m1 = mn1;

#pragma unroll
        for (int nt = 0; nt < 16; nt++) {
            o[nt][0] *= a0; o[nt][1] *= a0;
            o[nt][2] *= a1; o[nt][3] *= a1;
        }

        CP_WAIT1();          // V(kb) resident (pending: K(knext))
        __syncthreads();

        // ---- O += Ph Vh + Pl Vh + Ph Vl
#pragma unroll
        for (int js = 0; js < 4; js++) {
            float* t0 = s[2 * js];
            float* t1 = s[2 * js + 1];
            uint32_t ph[4], pl[4];
            ph[0] = pack2bf(t0[0], t0[1]);
            ph[1] = pack2bf(t0[2], t0[3]);
            ph[2] = pack2bf(t1[0], t1[1]);
            ph[3] = pack2bf(t1[2], t1[3]);
            float r00 = t0[0] - __bfloat162float(__float2bfloat16(t0[0]));
            float r01 = t0[1] - __bfloat162float(__float2bfloat16(t0[1]));
            float r02 = t0[2] - __bfloat162float(__float2bfloat16(t0[2]));
            float r03 = t0[3] - __bfloat162float(__float2bfloat16(t0[3]));
            float r10 = t1[0] - __bfloat162float(__float2bfloat16(t1[0]));
            float r11 = t1[1] - __bfloat162float(__float2bfloat16(t1[1]));
            float r12 = t1[2] - __bfloat162float(__float2bfloat16(t1[2]));
            float r13 = t1[3] - __bfloat162float(__float2bfloat16(t1[3]));
            pl[0] = pack2bf(r00, r01);
            pl[1] = pack2bf(r02, r03);
            pl[2] = pack2bf(r10, r11);
            pl[3] = pack2bf(r12, r13);

            uint32_t vbase = (uint32_t)(js * 16 * AT_ROWB) + voff;
#pragma unroll
            for (int dp = 0; dp < 8; dp++) {
                uint32_t vh4[4], vl4[4];
                ldm_x4_trans(vh4, VH_u + vbase + dp * 32);
                mma_bf16(o[2 * dp],     ph, vh4);
                mma_bf16(o[2 * dp + 1], ph, vh4 + 2);
                mma_bf16(o[2 * dp],     pl, vh4);
                mma_bf16(o[2 * dp + 1], pl, vh4 + 2);
                ldm_x4_trans(vl4, VL_u + vbase + dp * 32);
                mma_bf16(o[2 * dp],     ph, vl4);
                mma_bf16(o[2 * dp + 1], ph, vl4 + 2);
            }
        }

        __syncthreads();                       // all warps done reading V
        if (knext < khi) issueV(knext, khi);   // overlap V load with next S
        CP_COMMIT();
    }

    // ---- epilogue
    float inv0 = 1.0f / fmaxf(l0, 1e-30f);
    float inv1 = 1.0f / fmaxf(l1, 1e-30f);
    const int cb = h * HDIM + (lane & 3) * 2;
#pragma unroll
    for (int nt = 0; nt < 16; nt++) {
        float2 w0 = make_float2(o[nt][0] * inv0, o[nt][1] * inv0);
        float2 w1 = make_float2(o[nt][2] * inv1, o[nt][3] * inv1);
        *(float2*)(g_ctx + (size_t)r0g * EMBED + cb + nt * 8) = w0;
        *(float2*)(g_ctx + (size_t)r1g * EMBED + cb + nt * 8) = w1;
    }
}

// ============================================================================
// launch
// ============================================================================
extern "C" void kernel_launch(void* const* d_in, const int* in_sizes, int n_in,
                              void* d_out, int out_size)
{
    const float* x      = (const float*)d_in[0];
    const int*   cu     = (const int*)  d_in[1];
    const float* cosb   = (const float*)d_in[2];
    const float* sinb   = (const float*)d_in[3];
    const float* w_qkv  = (const float*)d_in[4];
    const float* b_qkv  = (const float*)d_in[5];
    const float* qw     = (const float*)d_in[6];
    const float* kw     = (const float*)d_in[7];
    const float* w_proj = (const float*)d_in[8];
    const float* b_proj = (const float*)d_in[9];
    float* out = (float*)d_out;
    const int ncu = in_sizes[1];

    float *qkv_p, *ctx_p;
    __nv_bfloat16 *Ax_p, *Actx_p, *Wtqkv_p, *Wtprj_p;
    cudaGetSymbolAddress((void**)&qkv_p,   g_qkv);
    cudaGetSymbolAddress((void**)&ctx_p,   g_ctx);
    cudaGetSymbolAddress((void**)&Ax_p,    g_Ax);
    cudaGetSymbolAddress((void**)&Actx_p,  g_Actx);
    cudaGetSymbolAddress((void**)&Wtqkv_p, g_Wtqkv);
    cudaGetSymbolAddress((void**)&Wtprj_p, g_Wtprj);

    cudaFuncSetAttribute(attn_mma, cudaFuncAttributeMaxDynamicSharedMemorySize, AT_SMEM_B);
    cudaFuncSetAttribute(gemm_mma, cudaFuncAttributeMaxDynamicSharedMemorySize, MM_SMEM);

    // split conversions
    conv_split_A<<<(SEQ * EMBED + 255) / 256, 256>>>(x, Ax_p, SEQ, EMBED);
    conv_split_Wt<<<dim3(EMBED / 32, QKV_N / 32), dim3(32, 8)>>>(w_qkv, Wtqkv_p, EMBED, QKV_N);
    conv_split_Wt<<<dim3(EMBED / 32, EMBED / 32), dim3(32, 8)>>>(w_proj, Wtprj_p, EMBED, EMBED);

    // 1) QKV = x @ w_qkv + b_qkv
    gemm_mma<<<dim3(QKV_N / MM_BN, SEQ / MM_BM), 256, MM_SMEM>>>(Ax_p, Wtqkv_p, b_qkv, qkv_p, QKV_N, K3);

    // 2) RMSNorm + RoPE + hi/lo split
    norm_rope_split<<<dim3(SEQ, NHEADS), 128>>>(cosb, sinb, qw, kw);

    // 3) tensor-core flash attention
    attn_mma<<<dim3(SEQ / 64, NHEADS), 128, AT_SMEM_B>>>(cu, ncu);

    // 4) out = ctx @ w_proj + b_proj
    conv_split_A<<<(SEQ * EMBED + 255) / 256, 256>>>(ctx_p, Actx_p, SEQ, EMBED);
    gemm_mma<<<dim3(EMBED / MM_BN, SEQ / MM_BM), 256, MM_SMEM>>>(Actx_p, Wtprj_p, b_proj, out, EMBED, K3);
}

// round 7
// speedup vs baseline: 3.7332x; 1.0139x over previous
#include <cuda_runtime.h>
#include <cuda_bf16.h>
#include <math.h>
#include <stdint.h>

#define SEQ       2048
#define EMBED     1536
#define NHEADS    12
#define HDIM      128
#define QKV_N     (3 * EMBED)         // 4608
#define K3        (3 * EMBED)         // tripled K for split-bf16 GEMM = 4608
#define D2        (HDIM / 2)          // 64
#define EPS       1e-5f
#define ATT_SCALE 0.08838834764831843f   // 1/sqrt(128)

// ---------------- scratch (device globals; no runtime allocation) ----------------
__device__ float g_qkv[SEQ * QKV_N];                    // [s][3E] fp32
__device__ __nv_bfloat16 g_Ax   [SEQ * K3];             // split A for QKV gemm
__device__ __nv_bfloat16 g_Actx [SEQ * K3];             // split A for proj gemm (written by attn)
__device__ __nv_bfloat16 g_Wtqkv[QKV_N * K3];           // W_qkv^T split  (N x 3K)
__device__ __nv_bfloat16 g_Wtprj[EMBED * K3];           // W_proj^T split (N x 3K)
// attention operands, split hi/lo bf16, layout [h][s][d]
__device__ __nv_bfloat16 g_qh[NHEADS * SEQ * HDIM];
__device__ __nv_bfloat16 g_ql[NHEADS * SEQ * HDIM];
__device__ __nv_bfloat16 g_kh[NHEADS * SEQ * HDIM];
__device__ __nv_bfloat16 g_kl[NHEADS * SEQ * HDIM];
__device__ __nv_bfloat16 g_vh[NHEADS * SEQ * HDIM];
__device__ __nv_bfloat16 g_vl[NHEADS * SEQ * HDIM];

// ============================================================================
// helpers (sm_100-legal PTX only)
// ============================================================================
__device__ __forceinline__ uint32_t smem_to_u32(const void* p) {
    uint32_t a;
    asm("{ .reg .u64 t; cvta.to.shared.u64 t, %1; cvt.u32.u64 %0, t; }" : "=r"(a) : "l"(p));
    return a;
}
#define CP_ASYNC16(saddr, gptr) \
    asm volatile("cp.async.cg.shared.global [%0], [%1], 16;" \
        :: "r"(saddr), "l"(gptr) : "memory")
#define CP_COMMIT() asm volatile("cp.async.commit_group;" ::: "memory")
#define CP_WAIT0()  asm volatile("cp.async.wait_group 0;" ::: "memory")
#define CP_WAIT1()  asm volatile("cp.async.wait_group 1;" ::: "memory")

__device__ __forceinline__ void ldm_x4(uint32_t* r, uint32_t addr) {
    asm volatile("ldmatrix.sync.aligned.m8n8.x4.shared.b16 {%0,%1,%2,%3}, [%4];"
        : "=r"(r[0]), "=r"(r[1]), "=r"(r[2]), "=r"(r[3]) : "r"(addr));
}
__device__ __forceinline__ void ldm_x4_trans(uint32_t* r, uint32_t addr) {
    asm volatile("ldmatrix.sync.aligned.m8n8.x4.trans.shared.b16 {%0,%1,%2,%3}, [%4];"
        : "=r"(r[0]), "=r"(r[1]), "=r"(r[2]), "=r"(r[3]) : "r"(addr));
}
__device__ __forceinline__ void mma_bf16(float* d, const uint32_t* a, const uint32_t* b) {
    asm volatile(
        "mma.sync.aligned.m16n8k16.row.col.f32.bf16.bf16.f32 "
        "{%0,%1,%2,%3}, {%4,%5,%6,%7}, {%8,%9}, {%0,%1,%2,%3};"
        : "+f"(d[0]), "+f"(d[1]), "+f"(d[2]), "+f"(d[3])
        : "r"(a[0]), "r"(a[1]), "r"(a[2]), "r"(a[3]), "r"(b[0]), "r"(b[1]));
}
__device__ __forceinline__ uint32_t pack2bf(float lo, float hi) {
    __nv_bfloat162 t = __floats2bfloat162_rn(lo, hi);
    return *(uint32_t*)&t;
}

// ============================================================================
// Split-bf16 conversion kernels
// ============================================================================
__global__ __launch_bounds__(256) void conv_split_A(
    const float* __restrict__ src, __nv_bfloat16* __restrict__ dst, int M, int K)
{
    int idx = blockIdx.x * 256 + threadIdx.x;
    if (idx >= M * K) return;
    int m = idx / K, k = idx - m * K;
    float x  = src[idx];
    __nv_bfloat16 hi = __float2bfloat16(x);
    __nv_bfloat16 lo = __float2bfloat16(x - __bfloat162float(hi));
    __nv_bfloat16* row = dst + (size_t)m * (3 * K);
    row[k]         = hi;
    row[K + k]     = lo;
    row[2 * K + k] = hi;
}

__global__ __launch_bounds__(256) void conv_split_Wt(
    const float* __restrict__ W, __nv_bfloat16* __restrict__ Wt, int K, int N)
{
    __shared__ float tile[32][33];
    int k0 = blockIdx.x * 32, n0 = blockIdx.y * 32;
    int tx = threadIdx.x, ty = threadIdx.y;   // block (32, 8)
#pragma unroll
    for (int r = 0; r < 32; r += 8)
        tile[ty + r][tx] = W[(size_t)(k0 + ty + r) * N + n0 + tx];
    __syncthreads();
#pragma unroll
    for (int r = 0; r < 32; r += 8) {
        int n = n0 + ty + r, k = k0 + tx;
        float x  = tile[tx][ty + r];
        __nv_bfloat16 hi = __float2bfloat16(x);
        __nv_bfloat16 lo = __float2bfloat16(x - __bfloat162float(hi));
        __nv_bfloat16* row = Wt + (size_t)n * (3 * K);
        row[k]         = hi;
        row[K + k]     = hi;
        row[2 * K + k] = lo;
    }
}

// ============================================================================
// mma.sync GEMM v4: C[M,N] = A[M,k3] @ Bt[N,k3]^T + bias[N]
// CTA 128x128, 4 warps (warp tile 64x64), BK=64, 3-stage cp.async ring.
// A read 2x, B read 2x per chunk (was 2x/4x) -> 1/3 less smem traffic.
// ============================================================================
#define MM_BM     128
#define MM_BN     128
#define MM_BK     64
#define MM_PADB   144                        // bytes per smem row (128 data + 16 pad)
#define MM_TILEB  (128 * MM_PADB)            // 18432 B per matrix per stage
#define MM_STAGEB (2 * MM_TILEB)             // 36864
#define MM_STAGES 3
#define MM_SMEM   (MM_STAGES * MM_STAGEB)    // 110592

__device__ __forceinline__ void mm_load_tile(
    const __nv_bfloat16* __restrict__ src, int row0, int k3, int chunk,
    uint32_t dstBase, int tid)
{
#pragma unroll
    for (int c2 = 0; c2 < 8; c2++) {
        int idx = c2 * 128 + tid;
        int row = idx >> 3;
        int col = (idx & 7) * 16;
        const char* g = (const char*)(src + (size_t)(row0 + row) * k3) + chunk * 128 + col;
        CP_ASYNC16(dstBase + (uint32_t)(row * MM_PADB + col), g);
    }
}

__global__ __launch_bounds__(128, 2) void gemm_mma(
    const __nv_bfloat16* __restrict__ A, const __nv_bfloat16* __restrict__ Bt,
    const float* __restrict__ bias, float* __restrict__ C, int N, int k3)
{
    extern __shared__ char mmsm[];
    const uint32_t S_u = smem_to_u32(mmsm);

    const int tid    = threadIdx.x;
    const int lane   = tid & 31;
    const int wid    = tid >> 5;
    const int warp_m = wid & 1;        // 2 warps over M: 64 rows each
    const int warp_n = wid >> 1;       // 2 warps over N: 64 cols each
    const int m0 = blockIdx.y * MM_BM;
    const int n0 = blockIdx.x * MM_BN;
    const int nchunk = k3 / MM_BK;     // 72

    float acc[4][8][4];
#pragma unroll
    for (int mt = 0; mt < 4; mt++)
#pragma unroll
        for (int nt = 0; nt < 8; nt++)
#pragma unroll
            for (int q = 0; q < 4; q++) acc[mt][nt][q] = 0.f;

    const uint32_t aFrag = (uint32_t)((warp_m * 64 + (lane & 15)) * MM_PADB + (lane >> 4) * 16);
    const uint32_t bFrag = (uint32_t)((warp_n * 64 + ((lane >> 4) << 3) + (lane & 7)) * MM_PADB
                                      + ((lane >> 3) & 1) * 16);

    // prologue: load chunks 0,1 into stages 0,1
    mm_load_tile(A,  m0, k3, 0, S_u,             tid);
    mm_load_tile(Bt, n0, k3, 0, S_u + MM_TILEB,  tid);
    CP_COMMIT();
    mm_load_tile(A,  m0, k3, 1, S_u + MM_STAGEB,            tid);
    mm_load_tile(Bt, n0, k3, 1, S_u + MM_STAGEB + MM_TILEB, tid);
    CP_COMMIT();

    int slot = 0;
    for (int c = 0; c < nchunk; ++c) {
        CP_WAIT1();          // chunk c resident
        __syncthreads();
        if (c + 2 < nchunk) {
            int ns = slot + 2; if (ns >= MM_STAGES) ns -= MM_STAGES;
            mm_load_tile(A,  m0, k3, c + 2, S_u + ns * MM_STAGEB,            tid);
            mm_load_tile(Bt, n0, k3, c + 2, S_u + ns * MM_STAGEB + MM_TILEB, tid);
        }
        CP_COMMIT();         // commit (possibly empty) to keep group count

        const uint32_t Au = S_u + slot * MM_STAGEB;
        const uint32_t Bu = Au + MM_TILEB;
#pragma unroll
        for (int ks = 0; ks < 4; ++ks) {
            uint32_t af[4][4], bf[4][4];
#pragma unroll
            for (int mt = 0; mt < 4; mt++)
                ldm_x4(af[mt], Au + aFrag + mt * 16 * MM_PADB + ks * 32);
#pragma unroll
            for (int p = 0; p < 4; p++)
                ldm_x4(bf[p], Bu + bFrag + p * 16 * MM_PADB + ks * 32);
#pragma unroll
            for (int mt = 0; mt < 4; mt++)
#pragma unroll
                for (int p = 0; p < 4; p++) {
                    mma_bf16(acc[mt][2 * p],     af[mt], bf[p]);
                    mma_bf16(acc[mt][2 * p + 1], af[mt], bf[p] + 2);
                }
        }
        slot++; if (slot >= MM_STAGES) slot = 0;
    }

    // ---- epilogue with bias
    const int erow = lane >> 2;
    const int ecol = (lane & 3) * 2;
#pragma unroll
    for (int mt = 0; mt < 4; mt++) {
        int row = m0 + warp_m * 64 + mt * 16 + erow;
#pragma unroll
        for (int nt = 0; nt < 8; nt++) {
            int col = n0 + warp_n * 64 + nt * 8 + ecol;
            float b0 = bias[col], b1 = bias[col + 1];
            float* c0 = C + (size_t)row * N + col;
            float* c1 = C + (size_t)(row + 8) * N + col;
            c0[0] = acc[mt][nt][0] + b0;
            c0[1] = acc[mt][nt][1] + b1;
            c1[0] = acc[mt][nt][2] + b0;
            c1[1] = acc[mt][nt][3] + b1;
        }
    }
}

// ============================================================================
// RMSNorm + RoPE + split into hi/lo bf16, layout [h][s][d]
// ============================================================================
__global__ __launch_bounds__(128) void norm_rope_split(
    const float* __restrict__ cosb, const float* __restrict__ sinb,
    const float* __restrict__ qw,   const float* __restrict__ kw)
{
    const int s = blockIdx.x, h = blockIdx.y, d = threadIdx.x;
    __shared__ float sh[128];
    __shared__ float wsum[4];
    __shared__ float rms_sh;

    const float* base = g_qkv + (size_t)s * QKV_N + h * HDIM;
    const int d2 = (d < D2) ? d : d - D2;
    const float c  = cosb[s * D2 + d2];
    const float sn = sinb[s * D2 + d2];
    const size_t oidx = ((size_t)h * SEQ + s) * HDIM + d;

#pragma unroll
    for (int which = 0; which < 2; which++) {
        const float x = base[which * EMBED + d];
        float v = x * x;
#pragma unroll
        for (int o = 16; o; o >>= 1) v += __shfl_xor_sync(0xffffffffu, v, o);
        if ((d & 31) == 0) wsum[d >> 5] = v;
        __syncthreads();
        if (d == 0)
            rms_sh = rsqrtf((wsum[0] + wsum[1] + wsum[2] + wsum[3]) * (1.0f / HDIM) + EPS);
        __syncthreads();
        const float* w = which ? kw : qw;
        sh[d] = x * rms_sh * w[d];
        __syncthreads();
        float out;
        if (d < D2) out = sh[d] * c - sh[d + D2] * sn;
        else        out = sh[d] * c + sh[d - D2] * sn;
        __nv_bfloat16 hi = __float2bfloat16(out);
        __nv_bfloat16 lo = __float2bfloat16(out - __bfloat162float(hi));
        if (which == 0) { g_qh[oidx] = hi; g_ql[oidx] = lo; }
        else            { g_kh[oidx] = hi; g_kl[oidx] = lo; }
        __syncthreads();
    }
    float v = base[2 * EMBED + d];
    __nv_bfloat16 vh = __float2bfloat16(v);
    g_vh[oidx] = vh;
    g_vl[oidx] = __float2bfloat16(v - __bfloat162float(vh));
}

// ============================================================================
// tensor-core flash attention; epilogue writes split bf16 directly into g_Actx
// CTA = (64 queries, 1 head); 4 warps x 16 rows; BK=64 keys.
// ============================================================================
#define AT_PADE 136                       // bf16 elements per smem row
#define AT_ROWB (AT_PADE * 2)             // 272 bytes
#define AT_TILE (64 * AT_PADE)            // elements per tile
#define AT_SMEM_B (6 * AT_TILE * 2)       // 104448 bytes

__global__ __launch_bounds__(128) void attn_mma(const int* __restrict__ cu, int ncu)
{
    extern __shared__ __nv_bfloat16 asm_smem[];
    const uint32_t S_u  = smem_to_u32(asm_smem);
    const uint32_t QH_u = S_u;
    const uint32_t QL_u = S_u + 1 * AT_TILE * 2;
    const uint32_t KH_u = S_u + 2 * AT_TILE * 2;
    const uint32_t KL_u = S_u + 3 * AT_TILE * 2;
    const uint32_t VH_u = S_u + 4 * AT_TILE * 2;
    const uint32_t VL_u = S_u + 5 * AT_TILE * 2;
    __shared__ int scu[16];

    const int h    = blockIdx.y;
    const int q0   = blockIdx.x * 64;
    const int tid  = threadIdx.x;
    const int warp = tid >> 5;
    const int lane = tid & 31;

    const size_t hb = (size_t)h * SEQ * HDIM;

    auto issueK = [&](int kb, int khi) {
#pragma unroll
        for (int c = 0; c < 8; c++) {
            int i = c * 128 + tid;
            int row = i >> 4, ch = (i & 15) * 16;
            int gr = kb + row; if (gr > khi - 1) gr = khi - 1;
            uint32_t db = (uint32_t)(row * AT_ROWB + ch);
            CP_ASYNC16(KH_u + db, (const char*)(g_kh + hb + (size_t)gr * HDIM) + ch);
            CP_ASYNC16(KL_u + db, (const char*)(g_kl + hb + (size_t)gr * HDIM) + ch);
        }
    };
    auto issueV = [&](int kb, int khi) {
#pragma unroll
        for (int c = 0; c < 8; c++) {
            int i = c * 128 + tid;
            int row = i >> 4, ch = (i & 15) * 16;
            int gr = kb + row; if (gr > khi - 1) gr = khi - 1;
            uint32_t db = (uint32_t)(row * AT_ROWB + ch);
            CP_ASYNC16(VH_u + db, (const char*)(g_vh + hb + (size_t)gr * HDIM) + ch);
            CP_ASYNC16(VL_u + db, (const char*)(g_vl + hb + (size_t)gr * HDIM) + ch);
        }
    };

    if (tid < ncu && tid < 16) scu[tid] = cu[tid];
    __syncthreads();

    auto seg = [&](int p) {
        int sgi = 0;
        for (int i = 1; i < ncu; i++) sgi += (scu[i] <= p) ? 1 : 0;
        return sgi;
    };
    int klo, khi;
    {
        int s0 = seg(q0), s1 = seg(q0 + 63);
        if (s0 == s1) { klo = scu[s0]; khi = scu[s0 + 1]; }
        else          { klo = 0;       khi = SEQ; }
    }

    // prologue: group0 = Q + K(klo), group1 = V(klo)
#pragma unroll
    for (int c = 0; c < 8; c++) {
        int i = c * 128 + tid;
        int row = i >> 4, ch = (i & 15) * 16;
        CP_ASYNC16(QH_u + row * AT_ROWB + ch, (const char*)(g_qh + hb + (size_t)(q0 + row) * HDIM) + ch);
        CP_ASYNC16(QL_u + row * AT_ROWB + ch, (const char*)(g_ql + hb + (size_t)(q0 + row) * HDIM) + ch);
    }
    issueK(klo, khi);
    CP_COMMIT();
    issueV(klo, khi);
    CP_COMMIT();

    const int rloc  = lane >> 2;
    const int r0g   = q0 + warp * 16 + rloc;
    const int r1g   = r0g + 8;
    const int sq0   = seg(r0g), sq1 = seg(r1g);

    float m0 = -1e30f, m1 = -1e30f, l0 = 0.f, l1 = 0.f;
    float o[16][4];
#pragma unroll
    for (int nt = 0; nt < 16; nt++)
#pragma unroll
        for (int q = 0; q < 4; q++) o[nt][q] = 0.f;

    const uint32_t aoff = (uint32_t)((warp * 16 + (lane & 15)) * AT_ROWB + ((lane >> 4) * 8) * 2);
    const uint32_t boff = (uint32_t)(((lane & 7) + ((lane >> 4) << 3)) * AT_ROWB + (((lane >> 3) & 1) * 8) * 2);
    const uint32_t voff = (uint32_t)((((lane >> 3) & 1) * 8 + (lane & 7)) * AT_ROWB + ((lane >> 4) * 8) * 2);

    for (int kb = klo; kb < khi; kb += 64) {
        const int knext = kb + 64;

        CP_WAIT1();          // Q + K(kb) resident
        __syncthreads();

        // ---- S = scale * (Qh Kh^T + Ql Kh^T + Qh Kl^T)
        float s[8][4];
#pragma unroll
        for (int nt = 0; nt < 8; nt++)
#pragma unroll
            for (int q = 0; q < 4; q++) s[nt][q] = 0.f;

        const uint32_t aB[3] = { QH_u, QL_u, QH_u };
        const uint32_t bB[3] = { KH_u, KH_u, KL_u };
#pragma unroll
        for (int pass = 0; pass < 3; pass++) {
#pragma unroll
            for (int ks = 0; ks < 8; ks++) {
                uint32_t af[4];
                ldm_x4(af, aB[pass] + aoff + ks * 32);
#pragma unroll
                for (int np = 0; np < 4; np++) {
                    uint32_t bf[4];
                    ldm_x4(bf, bB[pass] + boff + np * 16 * AT_ROWB + ks * 32);
                    mma_bf16(s[2 * np],     af, bf);
                    mma_bf16(s[2 * np + 1], af, bf + 2);
                }
            }
        }

        __syncthreads();                       // all warps done reading K
        if (knext < khi) issueK(knext, khi);   // overlap K load with softmax+PV
        CP_COMMIT();

        // ---- scale + segment mask
#pragma unroll
        for (int nt = 0; nt < 8; nt++) {
            int j0 = kb + nt * 8 + (lane & 3) * 2;
            int j1 = j0 + 1;
            int sk0 = (j0 < khi) ? seg(j0) : -1;
            int sk1 = (j1 < khi) ? seg(j1) : -1;
            s[nt][0] = (sk0 == sq0) ? s[nt][0] * ATT_SCALE : -1e30f;
            s[nt][1] = (sk1 == sq0) ? s[nt][1] * ATT_SCALE : -1e30f;
            s[nt][2] = (sk0 == sq1) ? s[nt][2] * ATT_SCALE : -1e30f;
            s[nt][3] = (sk1 == sq1) ? s[nt][3] * ATT_SCALE : -1e30f;
        }

        // ---- online softmax (registers only)
        float mx0 = -1e30f, mx1 = -1e30f;
#pragma unroll
        for (int nt = 0; nt < 8; nt++) {
            mx0 = fmaxf(mx0, fmaxf(s[nt][0], s[nt][1]));
            mx1 = fmaxf(mx1, fmaxf(s[nt][2], s[nt][3]));
        }
        mx0 = fmaxf(mx0, __shfl_xor_sync(0xffffffffu, mx0, 1));
        mx0 = fmaxf(mx0, __shfl_xor_sync(0xffffffffu, mx0, 2));
        mx1 = fmaxf(mx1, __shfl_xor_sync(0xffffffffu, mx1, 1));
        mx1 = fmaxf(mx1, __shfl_xor_sync(0xffffffffu, mx1, 2));
        float mn0 = fmaxf(m0, mx0), mn1 = fmaxf(m1, mx1);
        bool live0 = mn0 > -1e29f, live1 = mn1 > -1e29f;
        float a0 = live0 ? __expf(m0 - mn0) : 1.f;
        float a1 = live1 ? __expf(m1 - mn1) : 1.f;
        float ls0 = 0.f, ls1 = 0.f;
#pragma unroll
        for (int nt = 0; nt < 8; nt++) {
            float p0 = live0 ? __expf(s[nt][0] - mn0) : 0.f;
            float p1 = live0 ? __expf(s[nt][1] - mn0) : 0.f;
            float p2 = live1 ? __expf(s[nt][2] - mn1) : 0.f;
            float p3 = live1 ? __expf(s[nt][3] - mn1) : 0.f;
            s[nt][0] = p0; s[nt][1] = p1; s[nt][2] = p2; s[nt][3] = p3;
            ls0 += p0 + p1; ls1 += p2 + p3;
        }
        ls0 += __shfl_xor_sync(0xffffffffu, ls0, 1);
        ls0 += __shfl_xor_sync(0xffffffffu, ls0, 2);
        ls1 += __shfl_xor_sync(0xffffffffu, ls1, 1);
        ls1 += __shfl_xor_sync(0xffffffffu, ls1, 2);
        l0 = l0 * a0 + ls0;  l1 = l1 * a1 + ls1;
        m0 = mn0;  m1 = mn1;

#pragma unroll
        for (int nt = 0; nt < 16; nt++) {
            o[nt][0] *= a0; o[nt][1] *= a0;
            o[nt][2] *= a1; o[nt][3] *= a1;
        }

        CP_WAIT1();          // V(kb) resident (pending: K(knext))
        __syncthreads();

        // ---- O += Ph Vh + Pl Vh + Ph Vl
#pragma unroll
        for (int js = 0; js < 4; js++) {
            float* t0 = s[2 * js];
            float* t1 = s[2 * js + 1];
            uint32_t ph[4], pl[4];
            ph[0] = pack2bf(t0[0], t0[1]);
            ph[1] = pack2bf(t0[2], t0[3]);
            ph[2] = pack2bf(t1[0], t1[1]);
            ph[3] = pack2bf(t1[2], t1[3]);
            float r00 = t0[0] - __bfloat162float(__float2bfloat16(t0[0]));
            float r01 = t0[1] - __bfloat162float(__float2bfloat16(t0[1]));
            float r02 = t0[2] - __bfloat162float(__float2bfloat16(t0[2]));
            float r03 = t0[3] - __bfloat162float(__float2bfloat16(t0[3]));
            float r10 = t1[0] - __bfloat162float(__float2bfloat16(t1[0]));
            float r11 = t1[1] - __bfloat162float(__float2bfloat16(t1[1]));
            float r12 = t1[2] - __bfloat162float(__float2bfloat16(t1[2]));
            float r13 = t1[3] - __bfloat162float(__float2bfloat16(t1[3]));
            pl[0] = pack2bf(r00, r01);
            pl[1] = pack2bf(r02, r03);
            pl[2] = pack2bf(r10, r11);
            pl[3] = pack2bf(r12, r13);

            uint32_t vbase = (uint32_t)(js * 16 * AT_ROWB) + voff;
#pragma unroll
            for (int dp = 0; dp < 8; dp++) {
                uint32_t vh4[4], vl4[4];
                ldm_x4_trans(vh4, VH_u + vbase + dp * 32);
                mma_bf16(o[2 * dp],     ph, vh4);
                mma_bf16(o[2 * dp + 1], ph, vh4 + 2);
                mma_bf16(o[2 * dp],     pl, vh4);
                mma_bf16(o[2 * dp + 1], pl, vh4 + 2);
                ldm_x4_trans(vl4, VL_u + vbase + dp * 32);
                mma_bf16(o[2 * dp],     ph, vl4);
                mma_bf16(o[2 * dp + 1], ph, vl4 + 2);
            }
        }

        __syncthreads();                       // all warps done reading V
        if (knext < khi) issueV(knext, khi);   // overlap V load with next S
        CP_COMMIT();
    }

    // ---- epilogue: write split bf16 (hi | lo | hi) directly into g_Actx [m][3K]
    float inv0 = 1.0f / fmaxf(l0, 1e-30f);
    float inv1 = 1.0f / fmaxf(l1, 1e-30f);
    const int cb = h * HDIM + (lane & 3) * 2;
    __nv_bfloat16* row0 = g_Actx + (size_t)r0g * K3;
    __nv_bfloat16* row1 = g_Actx + (size_t)r1g * K3;
#pragma unroll
    for (int nt = 0; nt < 16; nt++) {
        int k = cb + nt * 8;
        float v00 = o[nt][0] * inv0, v01 = o[nt][1] * inv0;
        float v10 = o[nt][2] * inv1, v11 = o[nt][3] * inv1;
        float h00 = __bfloat162float(__float2bfloat16(v00));
        float h01 = __bfloat162float(__float2bfloat16(v01));
        float h10 = __bfloat162float(__float2bfloat16(v10));
        float h11 = __bfloat162float(__float2bfloat16(v11));
        uint32_t hi0 = pack2bf(v00, v01);
        uint32_t hi1 = pack2bf(v10, v11);
        uint32_t lo0 = pack2bf(v00 - h00, v01 - h01);
        uint32_t lo1 = pack2bf(v10 - h10, v11 - h11);
        *(uint32_t*)(row0 + k)             = hi0;
        *(uint32_t*)(row0 + EMBED + k)     = lo0;
        *(uint32_t*)(row0 + 2 * EMBED + k) = hi0;
        *(uint32_t*)(row1 + k)             = hi1;
        *(uint32_t*)(row1 + EMBED + k)     = lo1;
        *(uint32_t*)(row1 + 2 * EMBED + k) = hi1;
    }
}

// ============================================================================
// launch
// ============================================================================
extern "C" void kernel_launch(void* const* d_in, const int* in_sizes, int n_in,
                              void* d_out, int out_size)
{
    const float* x      = (const float*)d_in[0];
    const int*   cu     = (const int*)  d_in[1];
    const float* cosb   = (const float*)d_in[2];
    const float* sinb   = (const float*)d_in[3];
    const float* w_qkv  = (const float*)d_in[4];
    const float* b_qkv  = (const float*)d_in[5];
    const float* qw     = (const float*)d_in[6];
    const float* kw     = (const float*)d_in[7];
    const float* w_proj = (const float*)d_in[8];
    const float* b_proj = (const float*)d_in[9];
    float* out = (float*)d_out;
    const int ncu = in_sizes[1];

    float* qkv_p;
    __nv_bfloat16 *Ax_p, *Actx_p, *Wtqkv_p, *Wtprj_p;
    cudaGetSymbolAddress((void**)&qkv_p,   g_qkv);
    cudaGetSymbolAddress((void**)&Ax_p,    g_Ax);
    cudaGetSymbolAddress((void**)&Actx_p,  g_Actx);
    cudaGetSymbolAddress((void**)&Wtqkv_p, g_Wtqkv);
    cudaGetSymbolAddress((void**)&Wtprj_p, g_Wtprj);

    cudaFuncSetAttribute(attn_mma, cudaFuncAttributeMaxDynamicSharedMemorySize, AT_SMEM_B);
    cudaFuncSetAttribute(gemm_mma, cudaFuncAttributeMaxDynamicSharedMemorySize, MM_SMEM);

    // split conversions
    conv_split_A<<<(SEQ * EMBED + 255) / 256, 256>>>(x, Ax_p, SEQ, EMBED);
    conv_split_Wt<<<dim3(EMBED / 32, QKV_N / 32), dim3(32, 8)>>>(w_qkv, Wtqkv_p, EMBED, QKV_N);
    conv_split_Wt<<<dim3(EMBED / 32, EMBED / 32), dim3(32, 8)>>>(w_proj, Wtprj_p, EMBED, EMBED);

    // 1) QKV = x @ w_qkv + b_qkv
    gemm_mma<<<dim3(QKV_N / MM_BN, SEQ / MM_BM), 128, MM_SMEM>>>(Ax_p, Wtqkv_p, b_qkv, qkv_p, QKV_N, K3);

    // 2) RMSNorm + RoPE + hi/lo split
    norm_rope_split<<<dim3(SEQ, NHEADS), 128>>>(cosb, sinb, qw, kw);

    // 3) tensor-core flash attention (writes split proj input directly)
    attn_mma<<<dim3(SEQ / 64, NHEADS), 128, AT_SMEM_B>>>(cu, ncu);

    // 4) out = ctx @ w_proj + b_proj
    gemm_mma<<<dim3(EMBED / MM_BN, SEQ / MM_BM), 128, MM_SMEM>>>(Actx_p, Wtprj_p, b_proj, out, EMBED, K3);
}

// round 8
// speedup vs baseline: 4.0717x; 1.0907x over previous
#include <cuda_runtime.h>
#include <cuda_bf16.h>
#include <math.h>
#include <stdint.h>

#define SEQ       2048
#define EMBED     1536
#define NHEADS    12
#define HDIM      128
#define QKV_N     (3 * EMBED)         // 4608
#define K2        (2 * EMBED)         // hi|lo layout width = 3072
#define D2        (HDIM / 2)          // 64
#define EPS       1e-5f
#define ATT_SCALE 0.08838834764831843f   // 1/sqrt(128)

// ---------------- scratch (device globals) ----------------
__device__ float g_qkv[SEQ * QKV_N];                    // [s][3E] fp32
__device__ __nv_bfloat16 g_Ax   [SEQ * K2];             // x split   [m][hi|lo]
__device__ __nv_bfloat16 g_Actx [SEQ * K2];             // ctx split [m][hi|lo] (written by attn)
__device__ __nv_bfloat16 g_Wtqkv[QKV_N * K2];           // W_qkv^T split  (N x 2K)
__device__ __nv_bfloat16 g_Wtprj[EMBED * K2];           // W_proj^T split (N x 2K)
// attention operands merged hi|lo: [h][s][256] (hi at d, lo at 128+d)
__device__ __nv_bfloat16 g_q2[NHEADS * SEQ * 2 * HDIM];
__device__ __nv_bfloat16 g_k2[NHEADS * SEQ * 2 * HDIM];
__device__ __nv_bfloat16 g_v2[NHEADS * SEQ * 2 * HDIM];

// ============================================================================
// helpers
// ============================================================================
__device__ __forceinline__ uint32_t smem_to_u32(const void* p) {
    uint32_t a;
    asm("{ .reg .u64 t; cvta.to.shared.u64 t, %1; cvt.u32.u64 %0, t; }" : "=r"(a) : "l"(p));
    return a;
}
#define CP_ASYNC16(saddr, gptr) \
    asm volatile("cp.async.cg.shared.global [%0], [%1], 16;" \
        :: "r"(saddr), "l"(gptr) : "memory")
#define CP_COMMIT() asm volatile("cp.async.commit_group;" ::: "memory")
#define CP_WAIT1()  asm volatile("cp.async.wait_group 1;" ::: "memory")

__device__ __forceinline__ void ldm_x4(uint32_t* r, uint32_t addr) {
    asm volatile("ldmatrix.sync.aligned.m8n8.x4.shared.b16 {%0,%1,%2,%3}, [%4];"
        : "=r"(r[0]), "=r"(r[1]), "=r"(r[2]), "=r"(r[3]) : "r"(addr));
}
__device__ __forceinline__ void ldm_x4_trans(uint32_t* r, uint32_t addr) {
    asm volatile("ldmatrix.sync.aligned.m8n8.x4.trans.shared.b16 {%0,%1,%2,%3}, [%4];"
        : "=r"(r[0]), "=r"(r[1]), "=r"(r[2]), "=r"(r[3]) : "r"(addr));
}
__device__ __forceinline__ void mma_bf16(float* d, const uint32_t* a, const uint32_t* b) {
    asm volatile(
        "mma.sync.aligned.m16n8k16.row.col.f32.bf16.bf16.f32 "
        "{%0,%1,%2,%3}, {%4,%5,%6,%7}, {%8,%9}, {%0,%1,%2,%3};"
        : "+f"(d[0]), "+f"(d[1]), "+f"(d[2]), "+f"(d[3])
        : "r"(a[0]), "r"(a[1]), "r"(a[2]), "r"(a[3]), "r"(b[0]), "r"(b[1]));
}
__device__ __forceinline__ uint32_t pack2bf(float lo, float hi) {
    __nv_bfloat162 t = __floats2bfloat162_rn(lo, hi);
    return *(uint32_t*)&t;
}

// ============================================================================
// Split-bf16 conversion kernels (hi|lo 2K layouts)
// ============================================================================
__global__ __launch_bounds__(256) void conv_split_A(
    const float* __restrict__ src, __nv_bfloat16* __restrict__ dst, int M, int K)
{
    int idx = blockIdx.x * 256 + threadIdx.x;
    if (idx >= M * K) return;
    int m = idx / K, k = idx - m * K;
    float x  = src[idx];
    __nv_bfloat16 hi = __float2bfloat16(x);
    __nv_bfloat16 lo = __float2bfloat16(x - __bfloat162float(hi));
    __nv_bfloat16* row = dst + (size_t)m * (2 * K);
    row[k]     = hi;
    row[K + k] = lo;
}

__global__ __launch_bounds__(256) void conv_split_Wt(
    const float* __restrict__ W, __nv_bfloat16* __restrict__ Wt, int K, int N)
{
    __shared__ float tile[32][33];
    int k0 = blockIdx.x * 32, n0 = blockIdx.y * 32;
    int tx = threadIdx.x, ty = threadIdx.y;   // block (32, 8)
#pragma unroll
    for (int r = 0; r < 32; r += 8)
        tile[ty + r][tx] = W[(size_t)(k0 + ty + r) * N + n0 + tx];
    __syncthreads();
#pragma unroll
    for (int r = 0; r < 32; r += 8) {
        int n = n0 + ty + r, k = k0 + tx;
        float x  = tile[tx][ty + r];
        __nv_bfloat16 hi = __float2bfloat16(x);
        __nv_bfloat16 lo = __float2bfloat16(x - __bfloat162float(hi));
        __nv_bfloat16* row = Wt + (size_t)n * (2 * K);
        row[k]     = hi;
        row[K + k] = lo;
    }
}

// ============================================================================
// mma.sync GEMM v5 (shared-operand split): C = A @ Bt^T + bias
// A,Bt in [*][2K] hi|lo layout. Per k32-chunk, 3 products from one load:
//   AhBh + AhBl + AlBh.  CTA 128x128, 4 warps (64x64), 3-stage ring.
// smem chunk row: 128B = [64B hi k32 | 64B lo k32] (+16B pad)
// ============================================================================
#define MM_BM     128
#define MM_BN     128
#define MM_PADB   144
#define MM_TILEB  (128 * MM_PADB)            // 18432
#define MM_STAGEB (2 * MM_TILEB)             // 36864
#define MM_STAGES 3
#define MM_SMEM   (MM_STAGES * MM_STAGEB)    // 110592

__device__ __forceinline__ void mm_load_tile(
    const __nv_bfloat16* __restrict__ src, int row0, int kk, int chunk,
    uint32_t dstBase, int tid)
{
#pragma unroll
    for (int c2 = 0; c2 < 8; c2++) {
        int idx = c2 * 128 + tid;
        int row = idx >> 3;
        int c16 = idx & 7;           // 0..3 hi, 4..7 lo
        const char* gb = (const char*)(src + (size_t)(row0 + row) * (2 * kk));
        const char* g  = (c16 < 4)
            ? gb + chunk * 64 + c16 * 16
            : gb + (size_t)kk * 2 + chunk * 64 + (c16 - 4) * 16;
        CP_ASYNC16(dstBase + (uint32_t)(row * MM_PADB + c16 * 16), g);
    }
}

__global__ __launch_bounds__(128, 2) void gemm_mma(
    const __nv_bfloat16* __restrict__ A, const __nv_bfloat16* __restrict__ Bt,
    const float* __restrict__ bias, float* __restrict__ C, int N, int kk)
{
    extern __shared__ char mmsm[];
    const uint32_t S_u = smem_to_u32(mmsm);

    const int tid    = threadIdx.x;
    const int lane   = tid & 31;
    const int wid    = tid >> 5;
    const int warp_m = wid & 1;        // 2 warps over M: 64 rows each
    const int warp_n = wid >> 1;       // 2 warps over N: 64 cols each
    const int m0 = blockIdx.y * MM_BM;
    const int n0 = blockIdx.x * MM_BN;
    const int nchunk = kk / 32;        // 48

    float acc[4][8][4];
#pragma unroll
    for (int mt = 0; mt < 4; mt++)
#pragma unroll
        for (int nt = 0; nt < 8; nt++)
#pragma unroll
            for (int q = 0; q < 4; q++) acc[mt][nt][q] = 0.f;

    const uint32_t aFrag = (uint32_t)((warp_m * 64 + (lane & 15)) * MM_PADB + (lane >> 4) * 16);
    const uint32_t bFrag = (uint32_t)((warp_n * 64 + ((lane >> 4) << 3) + (lane & 7)) * MM_PADB
                                      + ((lane >> 3) & 1) * 16);

    mm_load_tile(A,  m0, kk, 0, S_u,             tid);
    mm_load_tile(Bt, n0, kk, 0, S_u + MM_TILEB,  tid);
    CP_COMMIT();
    mm_load_tile(A,  m0, kk, 1, S_u + MM_STAGEB,            tid);
    mm_load_tile(Bt, n0, kk, 1, S_u + MM_STAGEB + MM_TILEB, tid);
    CP_COMMIT();

    int slot = 0;
    for (int c = 0; c < nchunk; ++c) {
        CP_WAIT1();
        __syncthreads();
        if (c + 2 < nchunk) {
            int ns = slot + 2; if (ns >= MM_STAGES) ns -= MM_STAGES;
            mm_load_tile(A,  m0, kk, c + 2, S_u + ns * MM_STAGEB,            tid);
            mm_load_tile(Bt, n0, kk, c + 2, S_u + ns * MM_STAGEB + MM_TILEB, tid);
        }
        CP_COMMIT();

        const uint32_t Au = S_u + slot * MM_STAGEB;
        const uint32_t Bu = Au + MM_TILEB;
#pragma unroll
        for (int ks = 0; ks < 2; ++ks) {
            uint32_t ah[4][4], bh[4][4], xl[4][4];
#pragma unroll
            for (int mt = 0; mt < 4; mt++)
                ldm_x4(ah[mt], Au + aFrag + mt * 16 * MM_PADB + ks * 32);
#pragma unroll
            for (int p = 0; p < 4; p++)
                ldm_x4(bh[p], Bu + bFrag + p * 16 * MM_PADB + ks * 32);
            // Ah * Bh
#pragma unroll
            for (int mt = 0; mt < 4; mt++)
#pragma unroll
                for (int p = 0; p < 4; p++) {
                    mma_bf16(acc[mt][2 * p],     ah[mt], bh[p]);
                    mma_bf16(acc[mt][2 * p + 1], ah[mt], bh[p] + 2);
                }
            // Ah * Bl
#pragma unroll
            for (int p = 0; p < 4; p++)
                ldm_x4(xl[p], Bu + bFrag + p * 16 * MM_PADB + 64 + ks * 32);
#pragma unroll
            for (int mt = 0; mt < 4; mt++)
#pragma unroll
                for (int p = 0; p < 4; p++) {
                    mma_bf16(acc[mt][2 * p],     ah[mt], xl[p]);
                    mma_bf16(acc[mt][2 * p + 1], ah[mt], xl[p] + 2);
                }
            // Al * Bh
#pragma unroll
            for (int mt = 0; mt < 4; mt++)
                ldm_x4(xl[mt], Au + aFrag + mt * 16 * MM_PADB + 64 + ks * 32);
#pragma unroll
            for (int mt = 0; mt < 4; mt++)
#pragma unroll
                for (int p = 0; p < 4; p++) {
                    mma_bf16(acc[mt][2 * p],     xl[mt], bh[p]);
                    mma_bf16(acc[mt][2 * p + 1], xl[mt], bh[p] + 2);
                }
        }
        slot++; if (slot >= MM_STAGES) slot = 0;
    }

    const int erow = lane >> 2;
    const int ecol = (lane & 3) * 2;
#pragma unroll
    for (int mt = 0; mt < 4; mt++) {
        int row = m0 + warp_m * 64 + mt * 16 + erow;
#pragma unroll
        for (int nt = 0; nt < 8; nt++) {
            int col = n0 + warp_n * 64 + nt * 8 + ecol;
            float b0 = bias[col], b1 = bias[col + 1];
            float* c0 = C + (size_t)row * N + col;
            float* c1 = C + (size_t)(row + 8) * N + col;
            c0[0] = acc[mt][nt][0] + b0;
            c0[1] = acc[mt][nt][1] + b1;
            c1[0] = acc[mt][nt][2] + b0;
            c1[1] = acc[mt][nt][3] + b1;
        }
    }
}

// ============================================================================
// RMSNorm + RoPE + hi/lo split into merged [h][s][256] layout
// ============================================================================
__global__ __launch_bounds__(128) void norm_rope_split(
    const float* __restrict__ cosb, const float* __restrict__ sinb,
    const float* __restrict__ qw,   const float* __restrict__ kw)
{
    const int s = blockIdx.x, h = blockIdx.y, d = threadIdx.x;
    __shared__ float sh[128];
    __shared__ float wsum[4];
    __shared__ float rms_sh;

    const float* base = g_qkv + (size_t)s * QKV_N + h * HDIM;
    const int d2 = (d < D2) ? d : d - D2;
    const float c  = cosb[s * D2 + d2];
    const float sn = sinb[s * D2 + d2];
    const size_t o2 = ((size_t)h * SEQ + s) * (2 * HDIM) + d;   // hi; lo at +HDIM

#pragma unroll
    for (int which = 0; which < 2; which++) {
        const float x = base[which * EMBED + d];
        float v = x * x;
#pragma unroll
        for (int o = 16; o; o >>= 1) v += __shfl_xor_sync(0xffffffffu, v, o);
        if ((d & 31) == 0) wsum[d >> 5] = v;
        __syncthreads();
        if (d == 0)
            rms_sh = rsqrtf((wsum[0] + wsum[1] + wsum[2] + wsum[3]) * (1.0f / HDIM) + EPS);
        __syncthreads();
        const float* w = which ? kw : qw;
        sh[d] = x * rms_sh * w[d];
        __syncthreads();
        float out;
        if (d < D2) out = sh[d] * c - sh[d + D2] * sn;
        else        out = sh[d] * c + sh[d - D2] * sn;
        __nv_bfloat16 hi = __float2bfloat16(out);
        __nv_bfloat16 lo = __float2bfloat16(out - __bfloat162float(hi));
        if (which == 0) { g_q2[o2] = hi; g_q2[o2 + HDIM] = lo; }
        else            { g_k2[o2] = hi; g_k2[o2 + HDIM] = lo; }
        __syncthreads();
    }
    float v = base[2 * EMBED + d];
    __nv_bfloat16 vh = __float2bfloat16(v);
    g_v2[o2]        = vh;
    g_v2[o2 + HDIM] = __float2bfloat16(v - __bfloat162float(vh));
}

// ============================================================================
// tensor-core flash attention (merged hi|lo tiles, Q fragments in registers)
// CTA = (64 queries, 1 head); 4 warps x 16 rows; BK=64 keys.
// tiles: 64 rows x 528B (256B hi | 256B lo | 16B pad)
// ============================================================================
#define AT_ROWB  528
#define AT_TILEB (64 * AT_ROWB)          // 33792
#define AT_SMEM_B (3 * AT_TILEB)         // 101376

__global__ __launch_bounds__(128) void attn_mma(const int* __restrict__ cu, int ncu)
{
    extern __shared__ char at_smem[];
    const uint32_t S_u = smem_to_u32(at_smem);
    const uint32_t Q_u = S_u;
    const uint32_t K_u = S_u + AT_TILEB;
    const uint32_t V_u = S_u + 2 * AT_TILEB;
    __shared__ int scu[16];

    const int h    = blockIdx.y;
    const int q0   = blockIdx.x * 64;
    const int tid  = threadIdx.x;
    const int warp = tid >> 5;
    const int lane = tid & 31;

    const size_t hb = (size_t)h * SEQ * (2 * HDIM);

    auto issueTile = [&](uint32_t dst, const __nv_bfloat16* src, int kb, int khi) {
#pragma unroll
        for (int c = 0; c < 16; c++) {
            int i = c * 128 + tid;
            int row = i >> 5, ch = (i & 31) * 16;
            int gr = kb + row; if (gr > khi - 1) gr = khi - 1;
            CP_ASYNC16(dst + (uint32_t)(row * AT_ROWB + ch),
                       (const char*)(src + hb + (size_t)gr * (2 * HDIM)) + ch);
        }
    };

    if (tid < ncu && tid < 16) scu[tid] = cu[tid];
    __syncthreads();

    auto seg = [&](int p) {
        int sgi = 0;
        for (int i = 1; i < ncu; i++) sgi += (scu[i] <= p) ? 1 : 0;
        return sgi;
    };
    int klo, khi;
    {
        int s0 = seg(q0), s1 = seg(q0 + 63);
        if (s0 == s1) { klo = scu[s0]; khi = scu[s0 + 1]; }
        else          { klo = 0;       khi = SEQ; }
    }

    // prologue: group0 = Q + K(klo); group1 = V(klo)
    issueTile(Q_u, g_q2, q0, q0 + 64);
    issueTile(K_u, g_k2, klo, khi);
    CP_COMMIT();
    issueTile(V_u, g_v2, klo, khi);
    CP_COMMIT();

    const int rloc  = lane >> 2;
    const int r0g   = q0 + warp * 16 + rloc;
    const int r1g   = r0g + 8;
    const int sq0   = seg(r0g), sq1 = seg(r1g);

    float m0 = -1e30f, m1 = -1e30f, l0 = 0.f, l1 = 0.f;
    float o[16][4];
#pragma unroll
    for (int nt = 0; nt < 16; nt++)
#pragma unroll
        for (int q = 0; q < 4; q++) o[nt][q] = 0.f;

    const uint32_t aoff = (uint32_t)((warp * 16 + (lane & 15)) * AT_ROWB + ((lane >> 4) * 8) * 2);
    const uint32_t boff = (uint32_t)(((lane & 7) + ((lane >> 4) << 3)) * AT_ROWB + (((lane >> 3) & 1) * 8) * 2);
    const uint32_t voff = (uint32_t)((((lane >> 3) & 1) * 8 + (lane & 7)) * AT_ROWB + ((lane >> 4) * 8) * 2);

    // Q resident after first wait; preload all Q fragments (hi+lo) into registers
    CP_WAIT1();
    __syncthreads();
    uint32_t qh[8][4], ql[8][4];
#pragma unroll
    for (int ks = 0; ks < 8; ks++) {
        ldm_x4(qh[ks], Q_u + aoff + ks * 32);
        ldm_x4(ql[ks], Q_u + aoff + 256 + ks * 32);
    }

    for (int kb = klo; kb < khi; kb += 64) {
        const int knext = kb + 64;

        CP_WAIT1();          // K(kb) resident
        __syncthreads();

        // ---- S = scale * (Qh Kh^T + Ql Kh^T + Qh Kl^T)
        float s[8][4];
#pragma unroll
        for (int nt = 0; nt < 8; nt++)
#pragma unroll
            for (int q = 0; q < 4; q++) s[nt][q] = 0.f;

#pragma unroll
        for (int ks = 0; ks < 8; ks++) {
            uint32_t kf[4][4];
#pragma unroll
            for (int np = 0; np < 4; np++)
                ldm_x4(kf[np], K_u + boff + np * 16 * AT_ROWB + ks * 32);
#pragma unroll
            for (int np = 0; np < 4; np++) {
                mma_bf16(s[2 * np],     qh[ks], kf[np]);
                mma_bf16(s[2 * np + 1], qh[ks], kf[np] + 2);
                mma_bf16(s[2 * np],     ql[ks], kf[np]);
                mma_bf16(s[2 * np + 1], ql[ks], kf[np] + 2);
            }
#pragma unroll
            for (int np = 0; np < 4; np++)
                ldm_x4(kf[np], K_u + boff + np * 16 * AT_ROWB + 256 + ks * 32);
#pragma unroll
            for (int np = 0; np < 4; np++) {
                mma_bf16(s[2 * np],     qh[ks], kf[np]);
                mma_bf16(s[2 * np + 1], qh[ks], kf[np] + 2);
            }
        }

        __syncthreads();                       // all warps done reading K
        if (knext < khi) issueTile(K_u, g_k2, knext, khi);
        CP_COMMIT();

        // ---- scale + segment mask
#pragma unroll
        for (int nt = 0; nt < 8; nt++) {
            int j0 = kb + nt * 8 + (lane & 3) * 2;
            int j1 = j0 + 1;
            int sk0 = (j0 < khi) ? seg(j0) : -1;
            int sk1 = (j1 < khi) ? seg(j1) : -1;
            s[nt][0] = (sk0 == sq0) ? s[nt][0] * ATT_SCALE : -1e30f;
            s[nt][1] = (sk1 == sq0) ? s[nt][1] * ATT_SCALE : -1e30f;
            s[nt][2] = (sk0 == sq1) ? s[nt][2] * ATT_SCALE : -1e30f;
            s[nt][3] = (sk1 == sq1) ? s[nt][3] * ATT_SCALE : -1e30f;
        }

        // ---- online softmax
        float mx0 = -1e30f, mx1 = -1e30f;
#pragma unroll
        for (int nt = 0; nt < 8; nt++) {
            mx0 = fmaxf(mx0, fmaxf(s[nt][0], s[nt][1]));
            mx1 = fmaxf(mx1, fmaxf(s[nt][2], s[nt][3]));
        }
        mx0 = fmaxf(mx0, __shfl_xor_sync(0xffffffffu, mx0, 1));
        mx0 = fmaxf(mx0, __shfl_xor_sync(0xffffffffu, mx0, 2));
        mx1 = fmaxf(mx1, __shfl_xor_sync(0xffffffffu, mx1, 1));
        mx1 = fmaxf(mx1, __shfl_xor_sync(0xffffffffu, mx1, 2));
        float mn0 = fmaxf(m0, mx0), mn1 = fmaxf(m1, mx1);
        bool live0 = mn0 > -1e29f, live1 = mn1 > -1e29f;
        float a0 = live0 ? __expf(m0 - mn0) : 1.f;
        float a1 = live1 ? __expf(m1 - mn1) : 1.f;
        float ls0 = 0.f, ls1 = 0.f;
#pragma unroll
        for (int nt = 0; nt < 8; nt++) {
            float p0 = live0 ? __expf(s[nt][0] - mn0) : 0.f;
            float p1 = live0 ? __expf(s[nt][1] - mn0) : 0.f;
            float p2 = live1 ? __expf(s[nt][2] - mn1) : 0.f;
            float p3 = live1 ? __expf(s[nt][3] - mn1) : 0.f;
            s[nt][0] = p0; s[nt][1] = p1; s[nt][2] = p2; s[nt][3] = p3;
            ls0 += p0 + p1; ls1 += p2 + p3;
        }
        ls0 += __shfl_xor_sync(0xffffffffu, ls0, 1);
        ls0 += __shfl_xor_sync(0xffffffffu, ls0, 2);
        ls1 += __shfl_xor_sync(0xffffffffu, ls1, 1);
        ls1 += __shfl_xor_sync(0xffffffffu, ls1, 2);
        l0 = l0 * a0 + ls0;  l1 = l1 * a1 + ls1;
        m0 = mn0;  m1 = mn1;

#pragma unroll
        for (int nt = 0; nt < 16; nt++) {
            o[nt][0] *= a0; o[nt][1] *= a0;
            o[nt][2] *= a1; o[nt][3] *= a1;
        }

        CP_WAIT1();          // V(kb) resident (pending: K(knext))
        __syncthreads();

        // ---- O += Ph Vh + Pl Vh + Ph Vl
#pragma unroll
        for (int js = 0; js < 4; js++) {
            float* t0 = s[2 * js];
            float* t1 = s[2 * js + 1];
            uint32_t ph[4], pl[4];
            ph[0] = pack2bf(t0[0], t0[1]);
            ph[1] = pack2bf(t0[2], t0[3]);
            ph[2] = pack2bf(t1[0], t1[1]);
            ph[3] = pack2bf(t1[2], t1[3]);
            float r00 = t0[0] - __bfloat162float(__float2bfloat16(t0[0]));
            float r01 = t0[1] - __bfloat162float(__float2bfloat16(t0[1]));
            float r02 = t0[2] - __bfloat162float(__float2bfloat16(t0[2]));
            float r03 = t0[3] - __bfloat162float(__float2bfloat16(t0[3]));
            float r10 = t1[0] - __bfloat162float(__float2bfloat16(t1[0]));
            float r11 = t1[1] - __bfloat162float(__float2bfloat16(t1[1]));
            float r12 = t1[2] - __bfloat162float(__float2bfloat16(t1[2]));
            float r13 = t1[3] - __bfloat162float(__float2bfloat16(t1[3]));
            pl[0] = pack2bf(r00, r01);
            pl[1] = pack2bf(r02, r03);
            pl[2] = pack2bf(r10, r11);
            pl[3] = pack2bf(r12, r13);

            uint32_t vbase = (uint32_t)(js * 16 * AT_ROWB) + voff;
#pragma unroll
            for (int dp = 0; dp < 8; dp++) {
                uint32_t vh4[4], vl4[4];
                ldm_x4_trans(vh4, V_u + vbase + dp * 32);
                mma_bf16(o[2 * dp],     ph, vh4);
                mma_bf16(o[2 * dp + 1], ph, vh4 + 2);
                mma_bf16(o[2 * dp],     pl, vh4);
                mma_bf16(o[2 * dp + 1], pl, vh4 + 2);
                ldm_x4_trans(vl4, V_u + vbase + 256 + dp * 32);
                mma_bf16(o[2 * dp],     ph, vl4);
                mma_bf16(o[2 * dp + 1], ph, vl4 + 2);
            }
        }

        __syncthreads();                       // all warps done reading V
        if (knext < khi) issueTile(V_u, g_v2, knext, khi);
        CP_COMMIT();
    }

    // ---- epilogue: write split bf16 (hi | lo) into g_Actx [m][2K]
    float inv0 = 1.0f / fmaxf(l0, 1e-30f);
    float inv1 = 1.0f / fmaxf(l1, 1e-30f);
    const int cb = h * HDIM + (lane & 3) * 2;
    __nv_bfloat16* row0 = g_Actx + (size_t)r0g * K2;
    __nv_bfloat16* row1 = g_Actx + (size_t)r1g * K2;
#pragma unroll
    for (int nt = 0; nt < 16; nt++) {
        int k = cb + nt * 8;
        float v00 = o[nt][0] * inv0, v01 = o[nt][1] * inv0;
        float v10 = o[nt][2] * inv1, v11 = o[nt][3] * inv1;
        float h00 = __bfloat162float(__float2bfloat16(v00));
        float h01 = __bfloat162float(__float2bfloat16(v01));
        float h10 = __bfloat162float(__float2bfloat16(v10));
        float h11 = __bfloat162float(__float2bfloat16(v11));
        *(uint32_t*)(row0 + k)         = pack2bf(v00, v01);
        *(uint32_t*)(row0 + EMBED + k) = pack2bf(v00 - h00, v01 - h01);
        *(uint32_t*)(row1 + k)         = pack2bf(v10, v11);
        *(uint32_t*)(row1 + EMBED + k) = pack2bf(v10 - h10, v11 - h11);
    }
}

// ============================================================================
// launch
// ============================================================================
extern "C" void kernel_launch(void* const* d_in, const int* in_sizes, int n_in,
                              void* d_out, int out_size)
{
    const float* x      = (const float*)d_in[0];
    const int*   cu     = (const int*)  d_in[1];
    const float* cosb   = (const float*)d_in[2];
    const float* sinb   = (const float*)d_in[3];
    const float* w_qkv  = (const float*)d_in[4];
    const float* b_qkv  = (const float*)d_in[5];
    const float* qw     = (const float*)d_in[6];
    const float* kw     = (const float*)d_in[7];
    const float* w_proj = (const float*)d_in[8];
    const float* b_proj = (const float*)d_in[9];
    float* out = (float*)d_out;
    const int ncu = in_sizes[1];

    float* qkv_p;
    __nv_bfloat16 *Ax_p, *Actx_p, *Wtqkv_p, *Wtprj_p;
    cudaGetSymbolAddress((void**)&qkv_p,   g_qkv);
    cudaGetSymbolAddress((void**)&Ax_p,    g_Ax);
    cudaGetSymbolAddress((void**)&Actx_p,  g_Actx);
    cudaGetSymbolAddress((void**)&Wtqkv_p, g_Wtqkv);
    cudaGetSymbolAddress((void**)&Wtprj_p, g_Wtprj);

    cudaFuncSetAttribute(attn_mma, cudaFuncAttributeMaxDynamicSharedMemorySize, AT_SMEM_B);
    cudaFuncSetAttribute(gemm_mma, cudaFuncAttributeMaxDynamicSharedMemorySize, MM_SMEM);

    // split conversions (hi|lo 2K layouts)
    conv_split_A<<<(SEQ * EMBED + 255) / 256, 256>>>(x, Ax_p, SEQ, EMBED);
    conv_split_Wt<<<dim3(EMBED / 32, QKV_N / 32), dim3(32, 8)>>>(w_qkv, Wtqkv_p, EMBED, QKV_N);
    conv_split_Wt<<<dim3(EMBED / 32, EMBED / 32), dim3(32, 8)>>>(w_proj, Wtprj_p, EMBED, EMBED);

    // 1) QKV = x @ w_qkv + b_qkv
    gemm_mma<<<dim3(QKV_N / MM_BN, SEQ / MM_BM), 128, MM_SMEM>>>(Ax_p, Wtqkv_p, b_qkv, qkv_p, QKV_N, EMBED);

    // 2) RMSNorm + RoPE + hi/lo split (merged layout)
    norm_rope_split<<<dim3(SEQ, NHEADS), 128>>>(cosb, sinb, qw, kw);

    // 3) tensor-core flash attention (writes split proj input directly)
    attn_mma<<<dim3(SEQ / 64, NHEADS), 128, AT_SMEM_B>>>(cu, ncu);

    // 4) out = ctx @ w_proj + b_proj
    gemm_mma<<<dim3(EMBED / MM_BN, SEQ / MM_BM), 128, MM_SMEM>>>(Actx_p, Wtprj_p, b_proj, out, EMBED, EMBED);
}